// round 13
// baseline (speedup 1.0000x reference)
#include <cuda_runtime.h>
#include <cstdint>

#define A_  10
#define B_  32
#define H_  512
#define H3_ 1536
#define S_  512
#define KSPL 4
#define CSPL 8
#define OUT_HH_OFF (A_*B_*S_)

typedef unsigned long long u64;
struct __align__(16) U2 { u64 x, y; };

// ---------------- scratch -----------------------------------------------
__device__ float g_M1[A_*H_*2];
__device__ float g_M2[A_*H_*8];
__device__ float g_cc[A_*H_];
__device__ float g_N1[A_*H_*2];
__device__ float g_N2[A_*H_*2];
__device__ float g_kk[A_*H_];
__device__ float g_P [A_*H3_*2];
__device__ float g_q [A_*H3_];
__device__ float g_ghp[KSPL*A_*B_*H3_];
__device__ float g_cp [CSPL*A_*B_*H_];

// ---------------- helpers -----------------------------------------------
__device__ __forceinline__ u64 pack2(float lo, float hi) {
    u64 r; asm("mov.b64 %0, {%1,%2};" : "=l"(r) : "f"(lo), "f"(hi)); return r;
}
__device__ __forceinline__ u64 bcast2(float x) { return pack2(x, x); }
__device__ __forceinline__ void unpack2(u64 v, float& lo, float& hi) {
    asm("mov.b64 {%0,%1}, %2;" : "=f"(lo), "=f"(hi) : "l"(v));
}
__device__ __forceinline__ u64 fma2(u64 a, u64 b, u64 c) {
    u64 d; asm("fma.rn.f32x2 %0, %1, %2, %3;" : "=l"(d) : "l"(a), "l"(b), "l"(c));
    return d;
}
__device__ __forceinline__ float tanh_ap(float x) {
    float y; asm("tanh.approx.f32 %0, %1;" : "=f"(y) : "f"(x)); return y;
}
__device__ __forceinline__ u64 tanh2(u64 v) {
    float a, b; unpack2(v, a, b);
    return pack2(tanh_ap(a), tanh_ap(b));
}
__device__ __forceinline__ float ftanh(float x) {
    x = fminf(fmaxf(x, -15.f), 15.f);
    float t = __expf(x + x);
    return fmaf(-2.f, __fdividef(1.f, t + 1.f), 1.f);
}
__device__ __forceinline__ float sigm(float x) {
    return __fdividef(1.f, 1.f + __expf(-x));
}

// =============================================================================
// kfoldIH: fold Wih -> P,q. grid 1920 (a x jt), block 256 (8 warps = 8 rows)
// =============================================================================
__global__ void kfoldIH(const float* __restrict__ Wih,
                        const float* __restrict__ Wdec,
                        const float* __restrict__ bdec,
                        const float* __restrict__ bih) {
    __shared__ __align__(16) float4 sDec[H_];
    int blk = blockIdx.x;
    int warp = threadIdx.x >> 5, lane = threadIdx.x & 31;
    int a = blk / 192, jt = blk % 192;
    for (int k = threadIdx.x; k < H_; k += 256) {
        sDec[k] = make_float4(Wdec[((size_t)a*H_ + k)*2 + 0],
                              Wdec[((size_t)a*H_ + k)*2 + 1],
                              bdec[(size_t)a*H_ + k], 0.f);
    }
    __syncthreads();
    int j = jt * 8 + warp;
    const float* row = Wih + ((size_t)a*H3_ + j)*H_;
    float p0 = 0.f, p1 = 0.f, q = 0.f;
#pragma unroll
    for (int i = 0; i < 4; i++) {
        int k0 = lane*4 + i*128;
        float4 w4 = *(const float4*)(row + k0);
        float4 d0 = sDec[k0+0], d1 = sDec[k0+1], d2 = sDec[k0+2], d3 = sDec[k0+3];
        p0 = fmaf(w4.x,d0.x, fmaf(w4.y,d1.x, fmaf(w4.z,d2.x, fmaf(w4.w,d3.x, p0))));
        p1 = fmaf(w4.x,d0.y, fmaf(w4.y,d1.y, fmaf(w4.z,d2.y, fmaf(w4.w,d3.y, p1))));
        q  = fmaf(w4.x,d0.z, fmaf(w4.y,d1.z, fmaf(w4.z,d2.z, fmaf(w4.w,d3.z, q ))));
    }
#pragma unroll
    for (int o = 16; o; o >>= 1) {
        p0 += __shfl_down_sync(0xffffffffu, p0, o);
        p1 += __shfl_down_sync(0xffffffffu, p1, o);
        q  += __shfl_down_sync(0xffffffffu, q , o);
    }
    if (lane == 0) {
        int r = a*H3_ + j;
        g_P[r*2+0] = p0; g_P[r*2+1] = p1;
        g_q[r] = q + bih[r];
    }
}

// =============================================================================
// kfoldAP: fold Wattn(first 2H)/Wptr -> M1,M2,cc,N1,N2,kk. grid 640, block 256
// =============================================================================
__global__ void kfoldAP(const float* __restrict__ Wattn,
                        const float* __restrict__ Wptr,
                        const float* __restrict__ Ws,
                        const float* __restrict__ bs,
                        const float* __restrict__ Wd,
                        const float* __restrict__ bd) {
    __shared__ __align__(16) float4 sMem[H_*3];
    int blk = blockIdx.x;
    int warp = threadIdx.x >> 5, lane = threadIdx.x & 31;
    int a = blk / 64, ht = blk % 64;
    float4* sFold = sMem;
    float4* sWdA  = sMem + H_;
    float4* sWdB  = sMem + 2*H_;
    for (int k = threadIdx.x; k < H_; k += 256) {
        sFold[k] = make_float4(Ws[k*2+0], Ws[k*2+1], bs[k], bd[(size_t)a*H_ + k]);
        const float* wd = Wd + ((size_t)a*H_ + k)*8;
        sWdA[k] = *(const float4*)(wd);
        sWdB[k] = *(const float4*)(wd + 4);
    }
    __syncthreads();
    int h = ht * 8 + warp;
    const float* ra = Wattn + ((size_t)a*H_ + h)*H3_;
    const float* rp = Wptr  + ((size_t)a*H_ + h)*(2*H_);
    float acc[16];
#pragma unroll
    for (int t = 0; t < 16; t++) acc[t] = 0.f;
#pragma unroll
    for (int i = 0; i < 4; i++) {
        int k0 = lane*4 + i*128;
        float4 a1 = *(const float4*)(ra + k0);
        float4 a2 = *(const float4*)(ra + H_ + k0);
        float4 q1 = *(const float4*)(rp + k0);
        float4 q2 = *(const float4*)(rp + H_ + k0);
        float wa1v[4] = {a1.x, a1.y, a1.z, a1.w};
        float wa2v[4] = {a2.x, a2.y, a2.z, a2.w};
        float wp1v[4] = {q1.x, q1.y, q1.z, q1.w};
        float wp2v[4] = {q2.x, q2.y, q2.z, q2.w};
#pragma unroll
        for (int c = 0; c < 4; c++) {
            int k = k0 + c;
            float wa1 = wa1v[c], wa2 = wa2v[c], wp1 = wp1v[c], wp2 = wp2v[c];
            float4 f  = sFold[k];
            float4 dA = sWdA[k];
            float4 dB = sWdB[k];
            acc[0]  = fmaf(wa1, f.x, acc[0]);
            acc[1]  = fmaf(wa1, f.y, acc[1]);
            acc[2]  = fmaf(wa2, dA.x, acc[2]);
            acc[3]  = fmaf(wa2, dA.y, acc[3]);
            acc[4]  = fmaf(wa2, dA.z, acc[4]);
            acc[5]  = fmaf(wa2, dA.w, acc[5]);
            acc[6]  = fmaf(wa2, dB.x, acc[6]);
            acc[7]  = fmaf(wa2, dB.y, acc[7]);
            acc[8]  = fmaf(wa2, dB.z, acc[8]);
            acc[9]  = fmaf(wa2, dB.w, acc[9]);
            acc[10] = fmaf(wa1, f.z, fmaf(wa2, f.w, acc[10]));
            acc[11] = fmaf(wp1, f.x, acc[11]);
            acc[12] = fmaf(wp1, f.y, acc[12]);
            acc[13] = fmaf(wp2, f.x, acc[13]);
            acc[14] = fmaf(wp2, f.y, acc[14]);
            acc[15] = fmaf(wp1 + wp2, f.z, acc[15]);
        }
    }
#pragma unroll
    for (int t = 0; t < 16; t++)
#pragma unroll
        for (int o = 16; o; o >>= 1)
            acc[t] += __shfl_down_sync(0xffffffffu, acc[t], o);
    if (lane == 0) {
        int r = a*H_ + h;
        g_M1[r*2+0] = acc[0];  g_M1[r*2+1] = acc[1];
#pragma unroll
        for (int f = 0; f < 8; f++) g_M2[r*8+f] = acc[2+f];
        g_cc[r] = acc[10];
        g_N1[r*2+0] = acc[11]; g_N1[r*2+1] = acc[12];
        g_N2[r*2+0] = acc[13]; g_N2[r*2+1] = acc[14];
        g_kk[r] = acc[15];
    }
}

// =============================================================================
// kgh: register-tiled GEMV bundle: ghp[ks][a][b][j] over k-chunk 128.
// grid 480 (a x jt12 x ks4), block 128 = 32 jg x 4 bg; thread = 4j x 4bp
// =============================================================================
__global__ void kgh(const float* __restrict__ Whh,
                    const float* __restrict__ hh) {
    __shared__ __align__(16) u64 sH[128*18];   // [k][bp] pad 18
    __shared__ float sW[128*17];               // slab [j][k16] pad 17
    int tid = threadIdx.x;
    int blk = blockIdx.x;
    int a = blk / 48, rem = blk % 48, jt = rem >> 2, ks = rem & 3;
    int k0 = ks * 128;
    int jg = tid & 31, bg = tid >> 5;

    for (int idx = tid; idx < 128*16; idx += 128) {
        int k = idx & 127, bp = idx >> 7;
        sH[k*18 + bp] = pack2(hh[(size_t)(2*bp  )*H_ + k0 + k],
                              hh[(size_t)(2*bp+1)*H_ + k0 + k]);
    }

    u64 acc[16];
#pragma unroll
    for (int t = 0; t < 16; t++) acc[t] = 0ull;

    const float* wbase = Whh + ((size_t)a*H3_ + jt*128)*H_ + k0;
#pragma unroll 1
    for (int slab = 0; slab < 8; slab++) {
        __syncthreads();
        {
            const float4* src = (const float4*)(wbase + (size_t)tid*H_ + slab*16);
            float4 v0 = src[0], v1 = src[1], v2 = src[2], v3 = src[3];
            float* d = sW + tid*17;
            d[0]=v0.x; d[1]=v0.y; d[2]=v0.z; d[3]=v0.w;
            d[4]=v1.x; d[5]=v1.y; d[6]=v1.z; d[7]=v1.w;
            d[8]=v2.x; d[9]=v2.y; d[10]=v2.z; d[11]=v2.w;
            d[12]=v3.x; d[13]=v3.y; d[14]=v3.z; d[15]=v3.w;
        }
        __syncthreads();
#pragma unroll
        for (int kk = 0; kk < 16; kk++) {
            int k = slab*16 + kk;
            u64 w0 = bcast2(sW[(jg     )*17 + kk]);
            u64 w1 = bcast2(sW[(jg + 32)*17 + kk]);
            u64 w2 = bcast2(sW[(jg + 64)*17 + kk]);
            u64 w3 = bcast2(sW[(jg + 96)*17 + kk]);
            const U2* hp = (const U2*)(sH + k*18 + bg*4);
            U2 hA = hp[0], hB = hp[1];
            acc[0]  = fma2(w0, hA.x, acc[0]);
            acc[1]  = fma2(w0, hA.y, acc[1]);
            acc[2]  = fma2(w0, hB.x, acc[2]);
            acc[3]  = fma2(w0, hB.y, acc[3]);
            acc[4]  = fma2(w1, hA.x, acc[4]);
            acc[5]  = fma2(w1, hA.y, acc[5]);
            acc[6]  = fma2(w1, hB.x, acc[6]);
            acc[7]  = fma2(w1, hB.y, acc[7]);
            acc[8]  = fma2(w2, hA.x, acc[8]);
            acc[9]  = fma2(w2, hA.y, acc[9]);
            acc[10] = fma2(w2, hB.x, acc[10]);
            acc[11] = fma2(w2, hB.y, acc[11]);
            acc[12] = fma2(w3, hA.x, acc[12]);
            acc[13] = fma2(w3, hA.y, acc[13]);
            acc[14] = fma2(w3, hB.x, acc[14]);
            acc[15] = fma2(w3, hB.y, acc[15]);
        }
    }

    float* outp = g_ghp + ((size_t)(ks*A_ + a)*B_)*H3_ + jt*128;
#pragma unroll
    for (int jj = 0; jj < 4; jj++) {
        int j = jg + 32*jj;
#pragma unroll
        for (int i = 0; i < 4; i++) {
            int bp = bg*4 + i;
            float lo, hi; unpack2(acc[jj*4+i], lo, hi);
            outp[(size_t)(2*bp  )*H3_ + j] = lo;
            outp[(size_t)(2*bp+1)*H3_ + j] = hi;
        }
    }
}

// =============================================================================
// kgates: GRU -> h_new (output). grid 640 x 256
// =============================================================================
__global__ void kgates(const float* __restrict__ dec,
                       const float* __restrict__ hh,
                       const float* __restrict__ bhh,
                       float* __restrict__ out) {
    int idx = blockIdx.x * 256 + threadIdx.x;
    int h  = idx & (H_-1);
    int ab = idx >> 9;
    int b  = ab & (B_-1);
    int a  = ab >> 5;
    float d0 = dec[b*2+0], d1 = dec[b*2+1];
    int base = a*H3_;
    float gi[3], gh[3];
#pragma unroll
    for (int g = 0; g < 3; g++) {
        int j = base + g*H_ + h;
        gi[g] = fmaf(g_P[j*2+0], d0, fmaf(g_P[j*2+1], d1, g_q[j]));
        float s = bhh[j];
#pragma unroll
        for (int ks = 0; ks < KSPL; ks++)
            s += g_ghp[((size_t)(ks*A_ + a)*B_ + b)*H3_ + g*H_ + h];
        gh[g] = s;
    }
    float r = sigm(gi[0] + gh[0]);
    float z = sigm(gi[1] + gh[1]);
    float n = ftanh(fmaf(r, gh[2], gi[2]));
    float hprev = hh[(size_t)b*H_ + h];
    out[OUT_HH_OFF + (size_t)ab*H_ + h] = fmaf(z, hprev - n, n);
}

// =============================================================================
// kc: c partials, register-tiled. grid 320 x 128
// =============================================================================
__global__ void kc(const float* __restrict__ Wattn,
                   const float* __restrict__ out) {
    __shared__ __align__(16) u64 sH[64*18];
    __shared__ float sW[128*17];
    int tid = threadIdx.x;
    int blk = blockIdx.x;
    int a = blk / 32, rem = blk % 32, ht = rem >> 3, cs = rem & 7;
    int k0 = cs * 64;
    int jg = tid & 31, bg = tid >> 5;
    const float* hn = out + OUT_HH_OFF + (size_t)a*B_*H_;

    for (int idx = tid; idx < 64*16; idx += 128) {
        int k = idx & 63, bp = idx >> 6;
        sH[k*18 + bp] = pack2(hn[(size_t)(2*bp  )*H_ + k0 + k],
                              hn[(size_t)(2*bp+1)*H_ + k0 + k]);
    }

    u64 acc[16];
#pragma unroll
    for (int t = 0; t < 16; t++) acc[t] = 0ull;

    const float* wbase = Wattn + ((size_t)(a*H_ + ht*128))*H3_ + 2*H_ + k0;
#pragma unroll 1
    for (int slab = 0; slab < 4; slab++) {
        __syncthreads();
        {
            const float4* src = (const float4*)(wbase + (size_t)tid*H3_ + slab*16);
            float4 v0 = src[0], v1 = src[1], v2 = src[2], v3 = src[3];
            float* d = sW + tid*17;
            d[0]=v0.x; d[1]=v0.y; d[2]=v0.z; d[3]=v0.w;
            d[4]=v1.x; d[5]=v1.y; d[6]=v1.z; d[7]=v1.w;
            d[8]=v2.x; d[9]=v2.y; d[10]=v2.z; d[11]=v2.w;
            d[12]=v3.x; d[13]=v3.y; d[14]=v3.z; d[15]=v3.w;
        }
        __syncthreads();
#pragma unroll
        for (int kk = 0; kk < 16; kk++) {
            int k = slab*16 + kk;
            u64 w0 = bcast2(sW[(jg     )*17 + kk]);
            u64 w1 = bcast2(sW[(jg + 32)*17 + kk]);
            u64 w2 = bcast2(sW[(jg + 64)*17 + kk]);
            u64 w3 = bcast2(sW[(jg + 96)*17 + kk]);
            const U2* hp = (const U2*)(sH + k*18 + bg*4);
            U2 hA = hp[0], hB = hp[1];
            acc[0]  = fma2(w0, hA.x, acc[0]);
            acc[1]  = fma2(w0, hA.y, acc[1]);
            acc[2]  = fma2(w0, hB.x, acc[2]);
            acc[3]  = fma2(w0, hB.y, acc[3]);
            acc[4]  = fma2(w1, hA.x, acc[4]);
            acc[5]  = fma2(w1, hA.y, acc[5]);
            acc[6]  = fma2(w1, hB.x, acc[6]);
            acc[7]  = fma2(w1, hB.y, acc[7]);
            acc[8]  = fma2(w2, hA.x, acc[8]);
            acc[9]  = fma2(w2, hA.y, acc[9]);
            acc[10] = fma2(w2, hB.x, acc[10]);
            acc[11] = fma2(w2, hB.y, acc[11]);
            acc[12] = fma2(w3, hA.x, acc[12]);
            acc[13] = fma2(w3, hA.y, acc[13]);
            acc[14] = fma2(w3, hB.x, acc[14]);
            acc[15] = fma2(w3, hB.y, acc[15]);
        }
    }

    float* outp = g_cp + ((size_t)(cs*A_ + a)*B_)*H_ + ht*128;
#pragma unroll
    for (int jj = 0; jj < 4; jj++) {
        int h = jg + 32*jj;
#pragma unroll
        for (int i = 0; i < 4; i++) {
            int bp = bg*4 + i;
            float lo, hi; unpack2(acc[jj*4+i], lo, hi);
            outp[(size_t)(2*bp  )*H_ + h] = lo;
            outp[(size_t)(2*bp+1)*H_ + h] = hi;
        }
    }
}

// =============================================================================
// kattn: score + softmax + context + pointer head. grid A*B, block 512 (1 s/thr)
// =============================================================================
__global__ void kattn(const float* __restrict__ stat,
                      const float* __restrict__ dyn,
                      const float* __restrict__ va,
                      const float* __restrict__ vp,
                      float* __restrict__ out) {
    __shared__ __align__(16) float sC[256*24];   // 24KB, reused for pointer phase
    __shared__ float red[48];
    __shared__ float sP[2];
    int ab = blockIdx.x;
    int a = ab >> 5, b = ab & 31;
    int tid = threadIdx.x, warp = tid >> 5, lane = tid & 31;
    int s = tid;

    // ---- phase 1: stage attention constants (tid<256 each stage 1 hp) ----
    if (tid < 256) {
        int hp = tid, h0 = hp*2;
        int r0 = a*H_ + h0, r1 = r0 + 1;
        float c0v = g_cc[r0], c1v = g_cc[r1];
#pragma unroll
        for (int cs = 0; cs < CSPL; cs++) {
            const float* cp = g_cp + ((size_t)(cs*A_ + a)*B_ + b)*H_ + h0;
            c0v += cp[0]; c1v += cp[1];
        }
        float* p = sC + hp*24;
        p[0] = g_M1[r0*2+0]; p[1] = g_M1[r1*2+0];
        p[2] = g_M1[r0*2+1]; p[3] = g_M1[r1*2+1];
#pragma unroll
        for (int f = 0; f < 8; f++) { p[4+2*f] = g_M2[r0*8+f]; p[5+2*f] = g_M2[r1*8+f]; }
        p[20] = c0v; p[21] = c1v; p[22] = va[r0]; p[23] = va[r1];
    }
    __syncthreads();

    float st0 = stat[((size_t)b*2+0)*S_ + s];
    float st1 = stat[((size_t)b*2+1)*S_ + s];
    u64 st0v = bcast2(st0), st1v = bcast2(st1);
    u64 dy[8];
#pragma unroll
    for (int f = 0; f < 8; f++)
        dy[f] = bcast2(dyn[(((size_t)a*B_ + b)*8 + f)*S_ + s]);

    u64 acc = 0ull;
#pragma unroll 4
    for (int hp = 0; hp < 256; hp++) {
        const U2* cp = (const U2*)(sC + hp*24);
        U2 q0 = cp[0], q1 = cp[1], q2 = cp[2], q3 = cp[3], q4 = cp[4], q5 = cp[5];
        u64 u = fma2(q0.x, st0v, q5.x);
        u = fma2(q0.y, st1v, u);
        u = fma2(q1.x, dy[0], u); u = fma2(q1.y, dy[1], u);
        u = fma2(q2.x, dy[2], u); u = fma2(q2.y, dy[3], u);
        u = fma2(q3.x, dy[4], u); u = fma2(q3.y, dy[5], u);
        u = fma2(q4.x, dy[6], u); u = fma2(q4.y, dy[7], u);
        acc = fma2(q5.y, tanh2(u), acc);
    }
    float a0, a1;
    unpack2(acc, a0, a1);
    float sc = a0 + a1;   // score for s

    // ---- phase 2: softmax + context (16 warps) ----
    float m = sc;
#pragma unroll
    for (int o = 16; o; o >>= 1) m = fmaxf(m, __shfl_xor_sync(0xffffffffu, m, o));
    if (lane == 0) red[warp] = m;
    __syncthreads();
    float mx = red[0];
#pragma unroll
    for (int w = 1; w < 16; w++) mx = fmaxf(mx, red[w]);
    __syncthreads();

    float e = __expf(sc - mx);
    float d  = e;
    float n0 = e * st0;
    float n1 = e * st1;
#pragma unroll
    for (int o = 16; o; o >>= 1) {
        d  += __shfl_xor_sync(0xffffffffu, d , o);
        n0 += __shfl_xor_sync(0xffffffffu, n0, o);
        n1 += __shfl_xor_sync(0xffffffffu, n1, o);
    }
    if (lane == 0) { red[warp] = d; red[16+warp] = n0; red[32+warp] = n1; }
    __syncthreads();
    if (tid == 0) {
        float D = 0.f, N0 = 0.f, N1 = 0.f;
#pragma unroll
        for (int w = 0; w < 16; w++) { D += red[w]; N0 += red[16+w]; N1 += red[32+w]; }
        sP[0] = N0 / D; sP[1] = N1 / D;
    }
    __syncthreads();
    float p0 = sP[0], p1 = sP[1];

    // ---- phase 3: pointer head (reuse sC) ----
    if (tid < 256) {
        int hp = tid, h0 = hp*2;
        int r0 = a*H_ + h0, r1 = r0 + 1;
        float d0 = fmaf(g_N2[r0*2+0], p0, fmaf(g_N2[r0*2+1], p1, g_kk[r0]));
        float d1 = fmaf(g_N2[r1*2+0], p0, fmaf(g_N2[r1*2+1], p1, g_kk[r1]));
        float* p = sC + hp*8;
        p[0] = g_N1[r0*2+0]; p[1] = g_N1[r1*2+0];
        p[2] = g_N1[r0*2+1]; p[3] = g_N1[r1*2+1];
        p[4] = d0; p[5] = d1; p[6] = vp[r0]; p[7] = vp[r1];
    }
    __syncthreads();

    u64 pacc = 0ull;
#pragma unroll 8
    for (int hp = 0; hp < 256; hp++) {
        const U2* cp = (const U2*)(sC + hp*8);
        U2 q0 = cp[0], q1 = cp[1];
        u64 u = fma2(q0.x, st0v, q1.x);
        u = fma2(q0.y, st1v, u);
        pacc = fma2(q1.y, tanh2(u), pacc);
    }
    unpack2(pacc, a0, a1);
    out[(size_t)ab*S_ + s] = a0 + a1;
}

// =============================================================================
extern "C" void kernel_launch(void* const* d_in, const int* in_sizes, int n_in,
                              void* d_out, int out_size) {
    const float* stat  = (const float*)d_in[0];
    const float* dyn   = (const float*)d_in[1];
    const float* dec   = (const float*)d_in[2];
    const float* hh    = (const float*)d_in[3];
    const float* Ws    = (const float*)d_in[4];
    const float* bs    = (const float*)d_in[5];
    const float* Wd    = (const float*)d_in[6];
    const float* bd    = (const float*)d_in[7];
    const float* Wdec  = (const float*)d_in[8];
    const float* bdec  = (const float*)d_in[9];
    const float* Wih   = (const float*)d_in[10];
    const float* Whh   = (const float*)d_in[11];
    const float* bih   = (const float*)d_in[12];
    const float* bhh   = (const float*)d_in[13];
    const float* va    = (const float*)d_in[14];
    const float* Wattn = (const float*)d_in[15];
    const float* vp    = (const float*)d_in[16];
    const float* Wptr  = (const float*)d_in[17];
    float* out = (float*)d_out;

    static cudaStream_t sA = nullptr, sB = nullptr;
    static cudaEvent_t evRoot = nullptr, evIH = nullptr, evAP = nullptr;
    if (sA == nullptr) {
        cudaStreamCreateWithFlags(&sA, cudaStreamNonBlocking);
        cudaStreamCreateWithFlags(&sB, cudaStreamNonBlocking);
        cudaEventCreateWithFlags(&evRoot, cudaEventDisableTiming);
        cudaEventCreateWithFlags(&evIH, cudaEventDisableTiming);
        cudaEventCreateWithFlags(&evAP, cudaEventDisableTiming);
    }

    cudaEventRecord(evRoot, 0);
    cudaStreamWaitEvent(sA, evRoot, 0);
    cudaStreamWaitEvent(sB, evRoot, 0);

    kfoldIH<<<1920, 256, 0, sA>>>(Wih, Wdec, bdec, bih);         // launch 1
    cudaEventRecord(evIH, sA);

    kgh    <<<480, 128>>>(Whh, hh);                               // launch 2
    cudaStreamWaitEvent(0, evIH, 0);   // kgates needs P,q
    kgates <<<640, 256>>>(dec, hh, bhh, out);                     // launch 3
    kc     <<<320, 128>>>(Wattn, out);                            // launch 4 (profiled)

    kfoldAP<<<640, 256, 0, sB>>>(Wattn, Wptr, Ws, bs, Wd, bd);    // launch 5, overlaps 2-4
    cudaEventRecord(evAP, sB);

    cudaStreamWaitEvent(0, evAP, 0);   // kattn needs M1,M2,cc,N*,kk
    kattn  <<<A_*B_, 512>>>(stat, dyn, va, vp, out);              // launch 6
}

// round 15
// speedup vs baseline: 1.3157x; 1.3157x over previous
#include <cuda_runtime.h>
#include <cstdint>

#define A_  10
#define B_  32
#define H_  512
#define H3_ 1536
#define S_  512
#define KSPL 4
#define CSPL 8
#define OUT_HH_OFF (A_*B_*S_)

typedef unsigned long long u64;
struct __align__(16) U2 { u64 x, y; };

// ---------------- scratch -----------------------------------------------
__device__ float g_M1[A_*H_*2];
__device__ float g_M2[A_*H_*8];
__device__ float g_cc[A_*H_];
__device__ float g_N1[A_*H_*2];
__device__ float g_N2[A_*H_*2];
__device__ float g_kk[A_*H_];
__device__ float g_P [A_*H3_*2];
__device__ float g_q [A_*H3_];
__device__ float g_ghp[KSPL*A_*B_*H3_];
__device__ float g_cp [CSPL*A_*B_*H_];
__device__ float g_scoreP[2*A_*B_*S_];   // [hh][ab][s]

// ---------------- helpers -----------------------------------------------
__device__ __forceinline__ u64 pack2(float lo, float hi) {
    u64 r; asm("mov.b64 %0, {%1,%2};" : "=l"(r) : "f"(lo), "f"(hi)); return r;
}
__device__ __forceinline__ u64 bcast2(float x) { return pack2(x, x); }
__device__ __forceinline__ void unpack2(u64 v, float& lo, float& hi) {
    asm("mov.b64 {%0,%1}, %2;" : "=f"(lo), "=f"(hi) : "l"(v));
}
__device__ __forceinline__ u64 fma2(u64 a, u64 b, u64 c) {
    u64 d; asm("fma.rn.f32x2 %0, %1, %2, %3;" : "=l"(d) : "l"(a), "l"(b), "l"(c));
    return d;
}
__device__ __forceinline__ float tanh_ap(float x) {
    float y; asm("tanh.approx.f32 %0, %1;" : "=f"(y) : "f"(x)); return y;
}
__device__ __forceinline__ u64 tanh2(u64 v) {
    float a, b; unpack2(v, a, b);
    return pack2(tanh_ap(a), tanh_ap(b));
}
__device__ __forceinline__ float ftanh(float x) {
    x = fminf(fmaxf(x, -15.f), 15.f);
    float t = __expf(x + x);
    return fmaf(-2.f, __fdividef(1.f, t + 1.f), 1.f);
}
__device__ __forceinline__ float sigm(float x) {
    return __fdividef(1.f, 1.f + __expf(-x));
}

// =============================================================================
// kfoldIH: fold Wih -> P,q. grid 1920 (a x jt), block 256 (8 warps = 8 rows)
// =============================================================================
__global__ void kfoldIH(const float* __restrict__ Wih,
                        const float* __restrict__ Wdec,
                        const float* __restrict__ bdec,
                        const float* __restrict__ bih) {
    __shared__ __align__(16) float4 sDec[H_];
    int blk = blockIdx.x;
    int warp = threadIdx.x >> 5, lane = threadIdx.x & 31;
    int a = blk / 192, jt = blk % 192;
    for (int k = threadIdx.x; k < H_; k += 256) {
        sDec[k] = make_float4(Wdec[((size_t)a*H_ + k)*2 + 0],
                              Wdec[((size_t)a*H_ + k)*2 + 1],
                              bdec[(size_t)a*H_ + k], 0.f);
    }
    __syncthreads();
    int j = jt * 8 + warp;
    const float* row = Wih + ((size_t)a*H3_ + j)*H_;
    float p0 = 0.f, p1 = 0.f, q = 0.f;
#pragma unroll
    for (int i = 0; i < 4; i++) {
        int k0 = lane*4 + i*128;
        float4 w4 = *(const float4*)(row + k0);
        float4 d0 = sDec[k0+0], d1 = sDec[k0+1], d2 = sDec[k0+2], d3 = sDec[k0+3];
        p0 = fmaf(w4.x,d0.x, fmaf(w4.y,d1.x, fmaf(w4.z,d2.x, fmaf(w4.w,d3.x, p0))));
        p1 = fmaf(w4.x,d0.y, fmaf(w4.y,d1.y, fmaf(w4.z,d2.y, fmaf(w4.w,d3.y, p1))));
        q  = fmaf(w4.x,d0.z, fmaf(w4.y,d1.z, fmaf(w4.z,d2.z, fmaf(w4.w,d3.z, q ))));
    }
#pragma unroll
    for (int o = 16; o; o >>= 1) {
        p0 += __shfl_down_sync(0xffffffffu, p0, o);
        p1 += __shfl_down_sync(0xffffffffu, p1, o);
        q  += __shfl_down_sync(0xffffffffu, q , o);
    }
    if (lane == 0) {
        int r = a*H3_ + j;
        g_P[r*2+0] = p0; g_P[r*2+1] = p1;
        g_q[r] = q + bih[r];
    }
}

// =============================================================================
// kfoldAP: fold Wattn(first 2H)/Wptr -> M1,M2,cc,N1,N2,kk. grid 640, block 256
// =============================================================================
__global__ void kfoldAP(const float* __restrict__ Wattn,
                        const float* __restrict__ Wptr,
                        const float* __restrict__ Ws,
                        const float* __restrict__ bs,
                        const float* __restrict__ Wd,
                        const float* __restrict__ bd) {
    __shared__ __align__(16) float4 sMem[H_*3];
    int blk = blockIdx.x;
    int warp = threadIdx.x >> 5, lane = threadIdx.x & 31;
    int a = blk / 64, ht = blk % 64;
    float4* sFold = sMem;
    float4* sWdA  = sMem + H_;
    float4* sWdB  = sMem + 2*H_;
    for (int k = threadIdx.x; k < H_; k += 256) {
        sFold[k] = make_float4(Ws[k*2+0], Ws[k*2+1], bs[k], bd[(size_t)a*H_ + k]);
        const float* wd = Wd + ((size_t)a*H_ + k)*8;
        sWdA[k] = *(const float4*)(wd);
        sWdB[k] = *(const float4*)(wd + 4);
    }
    __syncthreads();
    int h = ht * 8 + warp;
    const float* ra = Wattn + ((size_t)a*H_ + h)*H3_;
    const float* rp = Wptr  + ((size_t)a*H_ + h)*(2*H_);
    float acc[16];
#pragma unroll
    for (int t = 0; t < 16; t++) acc[t] = 0.f;
#pragma unroll
    for (int i = 0; i < 4; i++) {
        int k0 = lane*4 + i*128;
        float4 a1 = *(const float4*)(ra + k0);
        float4 a2 = *(const float4*)(ra + H_ + k0);
        float4 q1 = *(const float4*)(rp + k0);
        float4 q2 = *(const float4*)(rp + H_ + k0);
        float wa1v[4] = {a1.x, a1.y, a1.z, a1.w};
        float wa2v[4] = {a2.x, a2.y, a2.z, a2.w};
        float wp1v[4] = {q1.x, q1.y, q1.z, q1.w};
        float wp2v[4] = {q2.x, q2.y, q2.z, q2.w};
#pragma unroll
        for (int c = 0; c < 4; c++) {
            int k = k0 + c;
            float wa1 = wa1v[c], wa2 = wa2v[c], wp1 = wp1v[c], wp2 = wp2v[c];
            float4 f  = sFold[k];
            float4 dA = sWdA[k];
            float4 dB = sWdB[k];
            acc[0]  = fmaf(wa1, f.x, acc[0]);
            acc[1]  = fmaf(wa1, f.y, acc[1]);
            acc[2]  = fmaf(wa2, dA.x, acc[2]);
            acc[3]  = fmaf(wa2, dA.y, acc[3]);
            acc[4]  = fmaf(wa2, dA.z, acc[4]);
            acc[5]  = fmaf(wa2, dA.w, acc[5]);
            acc[6]  = fmaf(wa2, dB.x, acc[6]);
            acc[7]  = fmaf(wa2, dB.y, acc[7]);
            acc[8]  = fmaf(wa2, dB.z, acc[8]);
            acc[9]  = fmaf(wa2, dB.w, acc[9]);
            acc[10] = fmaf(wa1, f.z, fmaf(wa2, f.w, acc[10]));
            acc[11] = fmaf(wp1, f.x, acc[11]);
            acc[12] = fmaf(wp1, f.y, acc[12]);
            acc[13] = fmaf(wp2, f.x, acc[13]);
            acc[14] = fmaf(wp2, f.y, acc[14]);
            acc[15] = fmaf(wp1 + wp2, f.z, acc[15]);
        }
    }
#pragma unroll
    for (int t = 0; t < 16; t++)
#pragma unroll
        for (int o = 16; o; o >>= 1)
            acc[t] += __shfl_down_sync(0xffffffffu, acc[t], o);
    if (lane == 0) {
        int r = a*H_ + h;
        g_M1[r*2+0] = acc[0];  g_M1[r*2+1] = acc[1];
#pragma unroll
        for (int f = 0; f < 8; f++) g_M2[r*8+f] = acc[2+f];
        g_cc[r] = acc[10];
        g_N1[r*2+0] = acc[11]; g_N1[r*2+1] = acc[12];
        g_N2[r*2+0] = acc[13]; g_N2[r*2+1] = acc[14];
        g_kk[r] = acc[15];
    }
}

// =============================================================================
// kgh: register-tiled GEMV bundle, 32-wide slabs (coalesced 128B stage/thread).
// grid 480 (a x jt12 x ks4), block 128 = 32 jg x 4 bg; thread = 4j x 4bp
// =============================================================================
__global__ void kgh(const float* __restrict__ Whh,
                    const float* __restrict__ hh) {
    __shared__ __align__(16) u64 sH[128*18];   // [k][bp] pad 18 -> 18.4KB
    __shared__ float sW[128*33];               // slab [j][k32] pad 33 -> 16.9KB
    int tid = threadIdx.x;
    int blk = blockIdx.x;
    int a = blk / 48, rem = blk % 48, jt = rem >> 2, ks = rem & 3;
    int k0 = ks * 128;
    int jg = tid & 31, bg = tid >> 5;

    for (int idx = tid; idx < 128*16; idx += 128) {
        int k = idx & 127, bp = idx >> 7;
        sH[k*18 + bp] = pack2(hh[(size_t)(2*bp  )*H_ + k0 + k],
                              hh[(size_t)(2*bp+1)*H_ + k0 + k]);
    }

    u64 acc[16];
#pragma unroll
    for (int t = 0; t < 16; t++) acc[t] = 0ull;

    const float* wbase = Whh + ((size_t)a*H3_ + jt*128)*H_ + k0;
#pragma unroll 1
    for (int slab = 0; slab < 4; slab++) {
        __syncthreads();
        {   // stage w slab: row j=tid, 32 k (128B contiguous per thread)
            const float4* src = (const float4*)(wbase + (size_t)tid*H_ + slab*32);
            float* d = sW + tid*33;
#pragma unroll
            for (int i = 0; i < 8; i++) {
                float4 v = src[i];
                d[i*4+0]=v.x; d[i*4+1]=v.y; d[i*4+2]=v.z; d[i*4+3]=v.w;
            }
        }
        __syncthreads();
#pragma unroll
        for (int kk = 0; kk < 32; kk++) {
            int k = slab*32 + kk;
            u64 w0 = bcast2(sW[(jg     )*33 + kk]);
            u64 w1 = bcast2(sW[(jg + 32)*33 + kk]);
            u64 w2 = bcast2(sW[(jg + 64)*33 + kk]);
            u64 w3 = bcast2(sW[(jg + 96)*33 + kk]);
            const U2* hp = (const U2*)(sH + k*18 + bg*4);
            U2 hA = hp[0], hB = hp[1];
            acc[0]  = fma2(w0, hA.x, acc[0]);
            acc[1]  = fma2(w0, hA.y, acc[1]);
            acc[2]  = fma2(w0, hB.x, acc[2]);
            acc[3]  = fma2(w0, hB.y, acc[3]);
            acc[4]  = fma2(w1, hA.x, acc[4]);
            acc[5]  = fma2(w1, hA.y, acc[5]);
            acc[6]  = fma2(w1, hB.x, acc[6]);
            acc[7]  = fma2(w1, hB.y, acc[7]);
            acc[8]  = fma2(w2, hA.x, acc[8]);
            acc[9]  = fma2(w2, hA.y, acc[9]);
            acc[10] = fma2(w2, hB.x, acc[10]);
            acc[11] = fma2(w2, hB.y, acc[11]);
            acc[12] = fma2(w3, hA.x, acc[12]);
            acc[13] = fma2(w3, hA.y, acc[13]);
            acc[14] = fma2(w3, hB.x, acc[14]);
            acc[15] = fma2(w3, hB.y, acc[15]);
        }
    }

    float* outp = g_ghp + ((size_t)(ks*A_ + a)*B_)*H3_ + jt*128;
#pragma unroll
    for (int jj = 0; jj < 4; jj++) {
        int j = jg + 32*jj;
#pragma unroll
        for (int i = 0; i < 4; i++) {
            int bp = bg*4 + i;
            float lo, hi; unpack2(acc[jj*4+i], lo, hi);
            outp[(size_t)(2*bp  )*H3_ + j] = lo;
            outp[(size_t)(2*bp+1)*H3_ + j] = hi;
        }
    }
}

// =============================================================================
// kgates: GRU -> h_new (output). grid 640 x 256
// =============================================================================
__global__ void kgates(const float* __restrict__ dec,
                       const float* __restrict__ hh,
                       const float* __restrict__ bhh,
                       float* __restrict__ out) {
    int idx = blockIdx.x * 256 + threadIdx.x;
    int h  = idx & (H_-1);
    int ab = idx >> 9;
    int b  = ab & (B_-1);
    int a  = ab >> 5;
    float d0 = dec[b*2+0], d1 = dec[b*2+1];
    int base = a*H3_;
    float gi[3], gh[3];
#pragma unroll
    for (int g = 0; g < 3; g++) {
        int j = base + g*H_ + h;
        gi[g] = fmaf(g_P[j*2+0], d0, fmaf(g_P[j*2+1], d1, g_q[j]));
        float s = bhh[j];
#pragma unroll
        for (int ks = 0; ks < KSPL; ks++)
            s += g_ghp[((size_t)(ks*A_ + a)*B_ + b)*H3_ + g*H_ + h];
        gh[g] = s;
    }
    float r = sigm(gi[0] + gh[0]);
    float z = sigm(gi[1] + gh[1]);
    float n = ftanh(fmaf(r, gh[2], gi[2]));
    float hprev = hh[(size_t)b*H_ + h];
    out[OUT_HH_OFF + (size_t)ab*H_ + h] = fmaf(z, hprev - n, n);
}

// =============================================================================
// kc: c partials, register-tiled, 32-wide slabs. grid 320 x 128
// =============================================================================
__global__ void kc(const float* __restrict__ Wattn,
                   const float* __restrict__ out) {
    __shared__ __align__(16) u64 sH[64*18];    // 9.2KB
    __shared__ float sW[128*33];               // 16.9KB
    int tid = threadIdx.x;
    int blk = blockIdx.x;
    int a = blk / 32, rem = blk % 32, ht = rem >> 3, cs = rem & 7;
    int k0 = cs * 64;
    int jg = tid & 31, bg = tid >> 5;
    const float* hn = out + OUT_HH_OFF + (size_t)a*B_*H_;

    for (int idx = tid; idx < 64*16; idx += 128) {
        int k = idx & 63, bp = idx >> 6;
        sH[k*18 + bp] = pack2(hn[(size_t)(2*bp  )*H_ + k0 + k],
                              hn[(size_t)(2*bp+1)*H_ + k0 + k]);
    }

    u64 acc[16];
#pragma unroll
    for (int t = 0; t < 16; t++) acc[t] = 0ull;

    const float* wbase = Wattn + ((size_t)(a*H_ + ht*128))*H3_ + 2*H_ + k0;
#pragma unroll 1
    for (int slab = 0; slab < 2; slab++) {
        __syncthreads();
        {
            const float4* src = (const float4*)(wbase + (size_t)tid*H3_ + slab*32);
            float* d = sW + tid*33;
#pragma unroll
            for (int i = 0; i < 8; i++) {
                float4 v = src[i];
                d[i*4+0]=v.x; d[i*4+1]=v.y; d[i*4+2]=v.z; d[i*4+3]=v.w;
            }
        }
        __syncthreads();
#pragma unroll
        for (int kk = 0; kk < 32; kk++) {
            int k = slab*32 + kk;
            u64 w0 = bcast2(sW[(jg     )*33 + kk]);
            u64 w1 = bcast2(sW[(jg + 32)*33 + kk]);
            u64 w2 = bcast2(sW[(jg + 64)*33 + kk]);
            u64 w3 = bcast2(sW[(jg + 96)*33 + kk]);
            const U2* hp = (const U2*)(sH + k*18 + bg*4);
            U2 hA = hp[0], hB = hp[1];
            acc[0]  = fma2(w0, hA.x, acc[0]);
            acc[1]  = fma2(w0, hA.y, acc[1]);
            acc[2]  = fma2(w0, hB.x, acc[2]);
            acc[3]  = fma2(w0, hB.y, acc[3]);
            acc[4]  = fma2(w1, hA.x, acc[4]);
            acc[5]  = fma2(w1, hA.y, acc[5]);
            acc[6]  = fma2(w1, hB.x, acc[6]);
            acc[7]  = fma2(w1, hB.y, acc[7]);
            acc[8]  = fma2(w2, hA.x, acc[8]);
            acc[9]  = fma2(w2, hA.y, acc[9]);
            acc[10] = fma2(w2, hB.x, acc[10]);
            acc[11] = fma2(w2, hB.y, acc[11]);
            acc[12] = fma2(w3, hA.x, acc[12]);
            acc[13] = fma2(w3, hA.y, acc[13]);
            acc[14] = fma2(w3, hB.x, acc[14]);
            acc[15] = fma2(w3, hB.y, acc[15]);
        }
    }

    float* outp = g_cp + ((size_t)(cs*A_ + a)*B_)*H_ + ht*128;
#pragma unroll
    for (int jj = 0; jj < 4; jj++) {
        int h = jg + 32*jj;
#pragma unroll
        for (int i = 0; i < 4; i++) {
            int bp = bg*4 + i;
            float lo, hi; unpack2(acc[jj*4+i], lo, hi);
            outp[(size_t)(2*bp  )*H_ + h] = lo;
            outp[(size_t)(2*bp+1)*H_ + h] = hi;
        }
    }
}

// =============================================================================
// kscore: attention scores split over h-halves.
// grid 640 (ab x hh), block 256 (2 s per thread), 12KB smem
// =============================================================================
__global__ void kscore(const float* __restrict__ stat,
                       const float* __restrict__ dyn,
                       const float* __restrict__ va) {
    __shared__ __align__(16) float sC[128*24];
    int blk = blockIdx.x;
    int hh_ = blk & 1, ab = blk >> 1;
    int a = ab >> 5, b = ab & 31;
    int tid = threadIdx.x;

    if (tid < 128) {
        int hp = tid;
        int h0 = hh_*256 + hp*2;
        int r0 = a*H_ + h0, r1 = r0 + 1;
        float c0v = g_cc[r0], c1v = g_cc[r1];
#pragma unroll
        for (int cs = 0; cs < CSPL; cs++) {
            const float* cp = g_cp + ((size_t)(cs*A_ + a)*B_ + b)*H_ + h0;
            c0v += cp[0]; c1v += cp[1];
        }
        float* p = sC + hp*24;
        p[0] = g_M1[r0*2+0]; p[1] = g_M1[r1*2+0];
        p[2] = g_M1[r0*2+1]; p[3] = g_M1[r1*2+1];
#pragma unroll
        for (int f = 0; f < 8; f++) { p[4+2*f] = g_M2[r0*8+f]; p[5+2*f] = g_M2[r1*8+f]; }
        p[20] = c0v; p[21] = c1v; p[22] = va[r0]; p[23] = va[r1];
    }
    __syncthreads();

    int s = tid*2;
    float2 st0p = *(const float2*)(stat + ((size_t)b*2+0)*S_ + s);
    float2 st1p = *(const float2*)(stat + ((size_t)b*2+1)*S_ + s);
    u64 st0a = bcast2(st0p.x), st0b = bcast2(st0p.y);
    u64 st1a = bcast2(st1p.x), st1b = bcast2(st1p.y);
    u64 dya[8], dyb[8];
#pragma unroll
    for (int f = 0; f < 8; f++) {
        float2 d = *(const float2*)(dyn + (((size_t)a*B_ + b)*8 + f)*S_ + s);
        dya[f] = bcast2(d.x); dyb[f] = bcast2(d.y);
    }

    u64 acc0 = 0ull, acc1 = 0ull;
#pragma unroll 2
    for (int hp = 0; hp < 128; hp++) {
        const U2* cp = (const U2*)(sC + hp*24);
        U2 q0 = cp[0], q1 = cp[1], q2 = cp[2], q3 = cp[3], q4 = cp[4], q5 = cp[5];
        u64 u = fma2(q0.x, st0a, q5.x);
        u = fma2(q0.y, st1a, u);
        u = fma2(q1.x, dya[0], u); u = fma2(q1.y, dya[1], u);
        u = fma2(q2.x, dya[2], u); u = fma2(q2.y, dya[3], u);
        u = fma2(q3.x, dya[4], u); u = fma2(q3.y, dya[5], u);
        u = fma2(q4.x, dya[6], u); u = fma2(q4.y, dya[7], u);
        acc0 = fma2(q5.y, tanh2(u), acc0);
        u64 v = fma2(q0.x, st0b, q5.x);
        v = fma2(q0.y, st1b, v);
        v = fma2(q1.x, dyb[0], v); v = fma2(q1.y, dyb[1], v);
        v = fma2(q2.x, dyb[2], v); v = fma2(q2.y, dyb[3], v);
        v = fma2(q3.x, dyb[4], v); v = fma2(q3.y, dyb[5], v);
        v = fma2(q4.x, dyb[6], v); v = fma2(q4.y, dyb[7], v);
        acc1 = fma2(q5.y, tanh2(v), acc1);
    }
    float a0, a1, b0, b1;
    unpack2(acc0, a0, a1);
    unpack2(acc1, b0, b1);
    *(float2*)(g_scoreP + ((size_t)(hh_*A_*B_ + ab))*S_ + s) = make_float2(a0 + a1, b0 + b1);
}

// =============================================================================
// kfinal: softmax + context + pointer head. grid A*B, block 256 (2 s/thread)
// =============================================================================
__global__ void kfinal(const float* __restrict__ stat,
                       const float* __restrict__ vp,
                       float* __restrict__ out) {
    __shared__ float sC[256*8];
    __shared__ float red[32];
    __shared__ float sP[2];
    int ab = blockIdx.x;
    int a = ab >> 5, b = ab & 31;
    int tid = threadIdx.x, warp = tid >> 5, lane = tid & 31;
    int s = tid*2;

    float2 scA = *(const float2*)(g_scoreP + (size_t)ab*S_ + s);
    float2 scB = *(const float2*)(g_scoreP + ((size_t)(A_*B_ + ab))*S_ + s);
    float2 sc  = make_float2(scA.x + scB.x, scA.y + scB.y);
    float2 st0p = *(const float2*)(stat + ((size_t)b*2+0)*S_ + s);
    float2 st1p = *(const float2*)(stat + ((size_t)b*2+1)*S_ + s);

    float m = fmaxf(sc.x, sc.y);
#pragma unroll
    for (int o = 16; o; o >>= 1) m = fmaxf(m, __shfl_xor_sync(0xffffffffu, m, o));
    if (lane == 0) red[warp] = m;
    __syncthreads();
    float mx = red[0];
#pragma unroll
    for (int w = 1; w < 8; w++) mx = fmaxf(mx, red[w]);
    __syncthreads();

    float e0 = __expf(sc.x - mx), e1 = __expf(sc.y - mx);
    float d  = e0 + e1;
    float n0 = fmaf(e0, st0p.x, e1*st0p.y);
    float n1 = fmaf(e0, st1p.x, e1*st1p.y);
#pragma unroll
    for (int o = 16; o; o >>= 1) {
        d  += __shfl_xor_sync(0xffffffffu, d , o);
        n0 += __shfl_xor_sync(0xffffffffu, n0, o);
        n1 += __shfl_xor_sync(0xffffffffu, n1, o);
    }
    if (lane == 0) { red[warp] = d; red[8+warp] = n0; red[16+warp] = n1; }
    __syncthreads();
    if (tid == 0) {
        float D = 0.f, N0 = 0.f, N1 = 0.f;
#pragma unroll
        for (int w = 0; w < 8; w++) { D += red[w]; N0 += red[8+w]; N1 += red[16+w]; }
        sP[0] = N0 / D; sP[1] = N1 / D;
    }
    __syncthreads();
    float p0 = sP[0], p1 = sP[1];

    {
        int hp = tid, h0 = hp*2;
        int r0 = a*H_ + h0, r1 = r0 + 1;
        float d0 = fmaf(g_N2[r0*2+0], p0, fmaf(g_N2[r0*2+1], p1, g_kk[r0]));
        float d1 = fmaf(g_N2[r1*2+0], p0, fmaf(g_N2[r1*2+1], p1, g_kk[r1]));
        float* p = sC + hp*8;
        p[0] = g_N1[r0*2+0]; p[1] = g_N1[r1*2+0];
        p[2] = g_N1[r0*2+1]; p[3] = g_N1[r1*2+1];
        p[4] = d0; p[5] = d1; p[6] = vp[r0]; p[7] = vp[r1];
    }
    __syncthreads();

    u64 st0a = bcast2(st0p.x), st0b = bcast2(st0p.y);
    u64 st1a = bcast2(st1p.x), st1b = bcast2(st1p.y);

    u64 acc0 = 0ull, acc1 = 0ull;
#pragma unroll 4
    for (int hp = 0; hp < 256; hp++) {
        const U2* cp = (const U2*)(sC + hp*8);
        U2 q0 = cp[0], q1 = cp[1];
        u64 u = fma2(q0.x, st0a, q1.x);
        u = fma2(q0.y, st1a, u);
        acc0 = fma2(q1.y, tanh2(u), acc0);
        u64 v = fma2(q0.x, st0b, q1.x);
        v = fma2(q0.y, st1b, v);
        acc1 = fma2(q1.y, tanh2(v), acc1);
    }
    float a0, a1, b0, b1;
    unpack2(acc0, a0, a1);
    unpack2(acc1, b0, b1);
    *(float2*)(out + (size_t)ab*S_ + s) = make_float2(a0 + a1, b0 + b1);
}

// =============================================================================
extern "C" void kernel_launch(void* const* d_in, const int* in_sizes, int n_in,
                              void* d_out, int out_size) {
    const float* stat  = (const float*)d_in[0];
    const float* dyn   = (const float*)d_in[1];
    const float* dec   = (const float*)d_in[2];
    const float* hh    = (const float*)d_in[3];
    const float* Ws    = (const float*)d_in[4];
    const float* bs    = (const float*)d_in[5];
    const float* Wd    = (const float*)d_in[6];
    const float* bd    = (const float*)d_in[7];
    const float* Wdec  = (const float*)d_in[8];
    const float* bdec  = (const float*)d_in[9];
    const float* Wih   = (const float*)d_in[10];
    const float* Whh   = (const float*)d_in[11];
    const float* bih   = (const float*)d_in[12];
    const float* bhh   = (const float*)d_in[13];
    const float* va    = (const float*)d_in[14];
    const float* Wattn = (const float*)d_in[15];
    const float* vp    = (const float*)d_in[16];
    const float* Wptr  = (const float*)d_in[17];
    float* out = (float*)d_out;

    static cudaStream_t sA = nullptr, sB = nullptr;
    static cudaEvent_t evRoot = nullptr, evIH = nullptr, evAP = nullptr;
    if (sA == nullptr) {
        cudaStreamCreateWithFlags(&sA, cudaStreamNonBlocking);
        cudaStreamCreateWithFlags(&sB, cudaStreamNonBlocking);
        cudaEventCreateWithFlags(&evRoot, cudaEventDisableTiming);
        cudaEventCreateWithFlags(&evIH, cudaEventDisableTiming);
        cudaEventCreateWithFlags(&evAP, cudaEventDisableTiming);
    }

    cudaEventRecord(evRoot, 0);
    cudaStreamWaitEvent(sA, evRoot, 0);
    cudaStreamWaitEvent(sB, evRoot, 0);

    kfoldIH<<<1920, 256, 0, sA>>>(Wih, Wdec, bdec, bih);
    cudaEventRecord(evIH, sA);
    kfoldAP<<<640, 256, 0, sB>>>(Wattn, Wptr, Ws, bs, Wd, bd);
    cudaEventRecord(evAP, sB);

    kgh    <<<480, 128>>>(Whh, hh);
    cudaStreamWaitEvent(0, evIH, 0);   // kgates needs P,q
    kgates <<<640, 256>>>(dec, hh, bhh, out);
    kc     <<<320, 128>>>(Wattn, out);
    cudaStreamWaitEvent(0, evAP, 0);   // kscore needs M1,M2,cc
    kscore <<<640, 256>>>(stat, dyn, va);
    kfinal <<<A_*B_, 256>>>(stat, vp, out);
}

// round 16
// speedup vs baseline: 1.3482x; 1.0247x over previous
#include <cuda_runtime.h>
#include <cstdint>

#define A_  10
#define B_  32
#define H_  512
#define H3_ 1536
#define S_  512
#define KSPL 4
#define CSPL 8
#define OUT_HH_OFF (A_*B_*S_)

typedef unsigned long long u64;
struct __align__(16) U2 { u64 x, y; };

// ---------------- scratch -----------------------------------------------
__device__ float g_M1[A_*H_*2];
__device__ float g_M2[A_*H_*8];
__device__ float g_cc[A_*H_];
__device__ float g_N1[A_*H_*2];
__device__ float g_N2[A_*H_*2];
__device__ float g_kk[A_*H_];
__device__ float g_P [A_*H3_*2];
__device__ float g_q [A_*H3_];
__device__ float g_ghp[KSPL*A_*B_*H3_];
__device__ float g_cp [CSPL*A_*B_*H_];
__device__ float g_scoreP[2*A_*B_*S_];   // [hh][ab][s]

// ---------------- helpers -----------------------------------------------
__device__ __forceinline__ u64 pack2(float lo, float hi) {
    u64 r; asm("mov.b64 %0, {%1,%2};" : "=l"(r) : "f"(lo), "f"(hi)); return r;
}
__device__ __forceinline__ u64 bcast2(float x) { return pack2(x, x); }
__device__ __forceinline__ void unpack2(u64 v, float& lo, float& hi) {
    asm("mov.b64 {%0,%1}, %2;" : "=f"(lo), "=f"(hi) : "l"(v));
}
__device__ __forceinline__ u64 fma2(u64 a, u64 b, u64 c) {
    u64 d; asm("fma.rn.f32x2 %0, %1, %2, %3;" : "=l"(d) : "l"(a), "l"(b), "l"(c));
    return d;
}
__device__ __forceinline__ float tanh_ap(float x) {
    float y; asm("tanh.approx.f32 %0, %1;" : "=f"(y) : "f"(x)); return y;
}
__device__ __forceinline__ u64 tanh2(u64 v) {
    float a, b; unpack2(v, a, b);
    return pack2(tanh_ap(a), tanh_ap(b));
}
__device__ __forceinline__ float ftanh(float x) {
    x = fminf(fmaxf(x, -15.f), 15.f);
    float t = __expf(x + x);
    return fmaf(-2.f, __fdividef(1.f, t + 1.f), 1.f);
}
__device__ __forceinline__ float sigm(float x) {
    return __fdividef(1.f, 1.f + __expf(-x));
}

// =============================================================================
// kfoldIH: fold Wih -> P,q. grid 1920 (a x jt), block 256 (8 warps = 8 rows)
// =============================================================================
__global__ void kfoldIH(const float* __restrict__ Wih,
                        const float* __restrict__ Wdec,
                        const float* __restrict__ bdec,
                        const float* __restrict__ bih) {
    __shared__ __align__(16) float4 sDec[H_];
    int blk = blockIdx.x;
    int warp = threadIdx.x >> 5, lane = threadIdx.x & 31;
    int a = blk / 192, jt = blk % 192;
    for (int k = threadIdx.x; k < H_; k += 256) {
        sDec[k] = make_float4(Wdec[((size_t)a*H_ + k)*2 + 0],
                              Wdec[((size_t)a*H_ + k)*2 + 1],
                              bdec[(size_t)a*H_ + k], 0.f);
    }
    __syncthreads();
    int j = jt * 8 + warp;
    const float* row = Wih + ((size_t)a*H3_ + j)*H_;
    float p0 = 0.f, p1 = 0.f, q = 0.f;
#pragma unroll
    for (int i = 0; i < 4; i++) {
        int k0 = lane*4 + i*128;
        float4 w4 = *(const float4*)(row + k0);
        float4 d0 = sDec[k0+0], d1 = sDec[k0+1], d2 = sDec[k0+2], d3 = sDec[k0+3];
        p0 = fmaf(w4.x,d0.x, fmaf(w4.y,d1.x, fmaf(w4.z,d2.x, fmaf(w4.w,d3.x, p0))));
        p1 = fmaf(w4.x,d0.y, fmaf(w4.y,d1.y, fmaf(w4.z,d2.y, fmaf(w4.w,d3.y, p1))));
        q  = fmaf(w4.x,d0.z, fmaf(w4.y,d1.z, fmaf(w4.z,d2.z, fmaf(w4.w,d3.z, q ))));
    }
#pragma unroll
    for (int o = 16; o; o >>= 1) {
        p0 += __shfl_down_sync(0xffffffffu, p0, o);
        p1 += __shfl_down_sync(0xffffffffu, p1, o);
        q  += __shfl_down_sync(0xffffffffu, q , o);
    }
    if (lane == 0) {
        int r = a*H3_ + j;
        g_P[r*2+0] = p0; g_P[r*2+1] = p1;
        g_q[r] = q + bih[r];
    }
}

// =============================================================================
// kfoldAP: fold Wattn(first 2H)/Wptr -> M1,M2,cc,N1,N2,kk. grid 640, block 256
// =============================================================================
__global__ void kfoldAP(const float* __restrict__ Wattn,
                        const float* __restrict__ Wptr,
                        const float* __restrict__ Ws,
                        const float* __restrict__ bs,
                        const float* __restrict__ Wd,
                        const float* __restrict__ bd) {
    __shared__ __align__(16) float4 sMem[H_*3];
    int blk = blockIdx.x;
    int warp = threadIdx.x >> 5, lane = threadIdx.x & 31;
    int a = blk / 64, ht = blk % 64;
    float4* sFold = sMem;
    float4* sWdA  = sMem + H_;
    float4* sWdB  = sMem + 2*H_;
    for (int k = threadIdx.x; k < H_; k += 256) {
        sFold[k] = make_float4(Ws[k*2+0], Ws[k*2+1], bs[k], bd[(size_t)a*H_ + k]);
        const float* wd = Wd + ((size_t)a*H_ + k)*8;
        sWdA[k] = *(const float4*)(wd);
        sWdB[k] = *(const float4*)(wd + 4);
    }
    __syncthreads();
    int h = ht * 8 + warp;
    const float* ra = Wattn + ((size_t)a*H_ + h)*H3_;
    const float* rp = Wptr  + ((size_t)a*H_ + h)*(2*H_);
    float acc[16];
#pragma unroll
    for (int t = 0; t < 16; t++) acc[t] = 0.f;
#pragma unroll
    for (int i = 0; i < 4; i++) {
        int k0 = lane*4 + i*128;
        float4 a1 = *(const float4*)(ra + k0);
        float4 a2 = *(const float4*)(ra + H_ + k0);
        float4 q1 = *(const float4*)(rp + k0);
        float4 q2 = *(const float4*)(rp + H_ + k0);
        float wa1v[4] = {a1.x, a1.y, a1.z, a1.w};
        float wa2v[4] = {a2.x, a2.y, a2.z, a2.w};
        float wp1v[4] = {q1.x, q1.y, q1.z, q1.w};
        float wp2v[4] = {q2.x, q2.y, q2.z, q2.w};
#pragma unroll
        for (int c = 0; c < 4; c++) {
            int k = k0 + c;
            float wa1 = wa1v[c], wa2 = wa2v[c], wp1 = wp1v[c], wp2 = wp2v[c];
            float4 f  = sFold[k];
            float4 dA = sWdA[k];
            float4 dB = sWdB[k];
            acc[0]  = fmaf(wa1, f.x, acc[0]);
            acc[1]  = fmaf(wa1, f.y, acc[1]);
            acc[2]  = fmaf(wa2, dA.x, acc[2]);
            acc[3]  = fmaf(wa2, dA.y, acc[3]);
            acc[4]  = fmaf(wa2, dA.z, acc[4]);
            acc[5]  = fmaf(wa2, dA.w, acc[5]);
            acc[6]  = fmaf(wa2, dB.x, acc[6]);
            acc[7]  = fmaf(wa2, dB.y, acc[7]);
            acc[8]  = fmaf(wa2, dB.z, acc[8]);
            acc[9]  = fmaf(wa2, dB.w, acc[9]);
            acc[10] = fmaf(wa1, f.z, fmaf(wa2, f.w, acc[10]));
            acc[11] = fmaf(wp1, f.x, acc[11]);
            acc[12] = fmaf(wp1, f.y, acc[12]);
            acc[13] = fmaf(wp2, f.x, acc[13]);
            acc[14] = fmaf(wp2, f.y, acc[14]);
            acc[15] = fmaf(wp1 + wp2, f.z, acc[15]);
        }
    }
#pragma unroll
    for (int t = 0; t < 16; t++)
#pragma unroll
        for (int o = 16; o; o >>= 1)
            acc[t] += __shfl_down_sync(0xffffffffu, acc[t], o);
    if (lane == 0) {
        int r = a*H_ + h;
        g_M1[r*2+0] = acc[0];  g_M1[r*2+1] = acc[1];
#pragma unroll
        for (int f = 0; f < 8; f++) g_M2[r*8+f] = acc[2+f];
        g_cc[r] = acc[10];
        g_N1[r*2+0] = acc[11]; g_N1[r*2+1] = acc[12];
        g_N2[r*2+0] = acc[13]; g_N2[r*2+1] = acc[14];
        g_kk[r] = acc[15];
    }
}

// =============================================================================
// kgh: register-tiled GEMV, 64 j-rows/block, 32-wide slabs.
// grid 960 (a x jt24 x ks4), block 128 = 32 jg x 4 bg; thread = 2j x 4bp
// =============================================================================
__global__ void kgh(const float* __restrict__ Whh,
                    const float* __restrict__ hh) {
    __shared__ __align__(16) u64 sH[128*18];   // [k][bp] 18.4KB
    __shared__ float sW[64*33];                // slab [j][k32] 8.4KB
    int tid = threadIdx.x;
    int blk = blockIdx.x;
    int a = blk / 96, rem = blk % 96, jt = rem >> 2, ks = rem & 3;
    int k0 = ks * 128;
    int jg = tid & 31, bg = tid >> 5;

    for (int idx = tid; idx < 128*16; idx += 128) {
        int k = idx & 127, bp = idx >> 7;
        sH[k*18 + bp] = pack2(hh[(size_t)(2*bp  )*H_ + k0 + k],
                              hh[(size_t)(2*bp+1)*H_ + k0 + k]);
    }

    u64 acc[8];
#pragma unroll
    for (int t = 0; t < 8; t++) acc[t] = 0ull;

    int srow = tid & 63, shalf = tid >> 6;     // 64 rows x 2 k-halves
    const float* wbase = Whh + ((size_t)a*H3_ + jt*64)*H_ + k0;
#pragma unroll 1
    for (int slab = 0; slab < 4; slab++) {
        __syncthreads();
        {   // stage w slab: row srow, 16 k (64B contiguous per thread)
            const float4* src = (const float4*)(wbase + (size_t)srow*H_ + slab*32 + shalf*16);
            float* d = sW + srow*33 + shalf*16;
#pragma unroll
            for (int i = 0; i < 4; i++) {
                float4 v = src[i];
                d[i*4+0]=v.x; d[i*4+1]=v.y; d[i*4+2]=v.z; d[i*4+3]=v.w;
            }
        }
        __syncthreads();
#pragma unroll
        for (int kk = 0; kk < 32; kk++) {
            int k = slab*32 + kk;
            u64 w0 = bcast2(sW[(jg     )*33 + kk]);
            u64 w1 = bcast2(sW[(jg + 32)*33 + kk]);
            const U2* hp = (const U2*)(sH + k*18 + bg*4);
            U2 hA = hp[0], hB = hp[1];
            acc[0] = fma2(w0, hA.x, acc[0]);
            acc[1] = fma2(w0, hA.y, acc[1]);
            acc[2] = fma2(w0, hB.x, acc[2]);
            acc[3] = fma2(w0, hB.y, acc[3]);
            acc[4] = fma2(w1, hA.x, acc[4]);
            acc[5] = fma2(w1, hA.y, acc[5]);
            acc[6] = fma2(w1, hB.x, acc[6]);
            acc[7] = fma2(w1, hB.y, acc[7]);
        }
    }

    float* outp = g_ghp + ((size_t)(ks*A_ + a)*B_)*H3_ + jt*64;
#pragma unroll
    for (int jj = 0; jj < 2; jj++) {
        int j = jg + 32*jj;
#pragma unroll
        for (int i = 0; i < 4; i++) {
            int bp = bg*4 + i;
            float lo, hi; unpack2(acc[jj*4+i], lo, hi);
            outp[(size_t)(2*bp  )*H3_ + j] = lo;
            outp[(size_t)(2*bp+1)*H3_ + j] = hi;
        }
    }
}

// =============================================================================
// kgates: GRU -> h_new (output). grid 640 x 256
// =============================================================================
__global__ void kgates(const float* __restrict__ dec,
                       const float* __restrict__ hh,
                       const float* __restrict__ bhh,
                       float* __restrict__ out) {
    int idx = blockIdx.x * 256 + threadIdx.x;
    int h  = idx & (H_-1);
    int ab = idx >> 9;
    int b  = ab & (B_-1);
    int a  = ab >> 5;
    float d0 = dec[b*2+0], d1 = dec[b*2+1];
    int base = a*H3_;
    float gi[3], gh[3];
#pragma unroll
    for (int g = 0; g < 3; g++) {
        int j = base + g*H_ + h;
        gi[g] = fmaf(g_P[j*2+0], d0, fmaf(g_P[j*2+1], d1, g_q[j]));
        float s = bhh[j];
#pragma unroll
        for (int ks = 0; ks < KSPL; ks++)
            s += g_ghp[((size_t)(ks*A_ + a)*B_ + b)*H3_ + g*H_ + h];
        gh[g] = s;
    }
    float r = sigm(gi[0] + gh[0]);
    float z = sigm(gi[1] + gh[1]);
    float n = ftanh(fmaf(r, gh[2], gi[2]));
    float hprev = hh[(size_t)b*H_ + h];
    out[OUT_HH_OFF + (size_t)ab*H_ + h] = fmaf(z, hprev - n, n);
}

// =============================================================================
// kc: c partials, register-tiled, 64 h-rows/block, 32-wide slabs.
// grid 640 (a x ht8 x cs8), block 128 = 32 jg x 4 bg; thread = 2h x 4bp
// =============================================================================
__global__ void kc(const float* __restrict__ Wattn,
                   const float* __restrict__ out) {
    __shared__ __align__(16) u64 sH[64*18];    // 9.2KB
    __shared__ float sW[64*33];                // 8.4KB
    int tid = threadIdx.x;
    int blk = blockIdx.x;
    int a = blk / 64, rem = blk % 64, ht = rem >> 3, cs = rem & 7;
    int k0 = cs * 64;
    int jg = tid & 31, bg = tid >> 5;
    const float* hn = out + OUT_HH_OFF + (size_t)a*B_*H_;

    for (int idx = tid; idx < 64*16; idx += 128) {
        int k = idx & 63, bp = idx >> 6;
        sH[k*18 + bp] = pack2(hn[(size_t)(2*bp  )*H_ + k0 + k],
                              hn[(size_t)(2*bp+1)*H_ + k0 + k]);
    }

    u64 acc[8];
#pragma unroll
    for (int t = 0; t < 8; t++) acc[t] = 0ull;

    int srow = tid & 63, shalf = tid >> 6;
    const float* wbase = Wattn + ((size_t)(a*H_ + ht*64))*H3_ + 2*H_ + k0;
#pragma unroll 1
    for (int slab = 0; slab < 2; slab++) {
        __syncthreads();
        {
            const float4* src = (const float4*)(wbase + (size_t)srow*H3_ + slab*32 + shalf*16);
            float* d = sW + srow*33 + shalf*16;
#pragma unroll
            for (int i = 0; i < 4; i++) {
                float4 v = src[i];
                d[i*4+0]=v.x; d[i*4+1]=v.y; d[i*4+2]=v.z; d[i*4+3]=v.w;
            }
        }
        __syncthreads();
#pragma unroll
        for (int kk = 0; kk < 32; kk++) {
            int k = slab*32 + kk;
            u64 w0 = bcast2(sW[(jg     )*33 + kk]);
            u64 w1 = bcast2(sW[(jg + 32)*33 + kk]);
            const U2* hp = (const U2*)(sH + k*18 + bg*4);
            U2 hA = hp[0], hB = hp[1];
            acc[0] = fma2(w0, hA.x, acc[0]);
            acc[1] = fma2(w0, hA.y, acc[1]);
            acc[2] = fma2(w0, hB.x, acc[2]);
            acc[3] = fma2(w0, hB.y, acc[3]);
            acc[4] = fma2(w1, hA.x, acc[4]);
            acc[5] = fma2(w1, hA.y, acc[5]);
            acc[6] = fma2(w1, hB.x, acc[6]);
            acc[7] = fma2(w1, hB.y, acc[7]);
        }
    }

    float* outp = g_cp + ((size_t)(cs*A_ + a)*B_)*H_ + ht*64;
#pragma unroll
    for (int jj = 0; jj < 2; jj++) {
        int h = jg + 32*jj;
#pragma unroll
        for (int i = 0; i < 4; i++) {
            int bp = bg*4 + i;
            float lo, hi; unpack2(acc[jj*4+i], lo, hi);
            outp[(size_t)(2*bp  )*H_ + h] = lo;
            outp[(size_t)(2*bp+1)*H_ + h] = hi;
        }
    }
}

// =============================================================================
// kscore: attention scores split over h-halves.
// grid 640 (ab x hh), block 256 (2 s per thread), 12KB smem
// =============================================================================
__global__ void kscore(const float* __restrict__ stat,
                       const float* __restrict__ dyn,
                       const float* __restrict__ va) {
    __shared__ __align__(16) float sC[128*24];
    int blk = blockIdx.x;
    int hh_ = blk & 1, ab = blk >> 1;
    int a = ab >> 5, b = ab & 31;
    int tid = threadIdx.x;

    if (tid < 128) {
        int hp = tid;
        int h0 = hh_*256 + hp*2;
        int r0 = a*H_ + h0, r1 = r0 + 1;
        float c0v = g_cc[r0], c1v = g_cc[r1];
#pragma unroll
        for (int cs = 0; cs < CSPL; cs++) {
            const float* cp = g_cp + ((size_t)(cs*A_ + a)*B_ + b)*H_ + h0;
            c0v += cp[0]; c1v += cp[1];
        }
        float* p = sC + hp*24;
        p[0] = g_M1[r0*2+0]; p[1] = g_M1[r1*2+0];
        p[2] = g_M1[r0*2+1]; p[3] = g_M1[r1*2+1];
#pragma unroll
        for (int f = 0; f < 8; f++) { p[4+2*f] = g_M2[r0*8+f]; p[5+2*f] = g_M2[r1*8+f]; }
        p[20] = c0v; p[21] = c1v; p[22] = va[r0]; p[23] = va[r1];
    }
    __syncthreads();

    int s = tid*2;
    float2 st0p = *(const float2*)(stat + ((size_t)b*2+0)*S_ + s);
    float2 st1p = *(const float2*)(stat + ((size_t)b*2+1)*S_ + s);
    u64 st0a = bcast2(st0p.x), st0b = bcast2(st0p.y);
    u64 st1a = bcast2(st1p.x), st1b = bcast2(st1p.y);
    u64 dya[8], dyb[8];
#pragma unroll
    for (int f = 0; f < 8; f++) {
        float2 d = *(const float2*)(dyn + (((size_t)a*B_ + b)*8 + f)*S_ + s);
        dya[f] = bcast2(d.x); dyb[f] = bcast2(d.y);
    }

    u64 acc0 = 0ull, acc1 = 0ull;
#pragma unroll 2
    for (int hp = 0; hp < 128; hp++) {
        const U2* cp = (const U2*)(sC + hp*24);
        U2 q0 = cp[0], q1 = cp[1], q2 = cp[2], q3 = cp[3], q4 = cp[4], q5 = cp[5];
        u64 u = fma2(q0.x, st0a, q5.x);
        u = fma2(q0.y, st1a, u);
        u = fma2(q1.x, dya[0], u); u = fma2(q1.y, dya[1], u);
        u = fma2(q2.x, dya[2], u); u = fma2(q2.y, dya[3], u);
        u = fma2(q3.x, dya[4], u); u = fma2(q3.y, dya[5], u);
        u = fma2(q4.x, dya[6], u); u = fma2(q4.y, dya[7], u);
        acc0 = fma2(q5.y, tanh2(u), acc0);
        u64 v = fma2(q0.x, st0b, q5.x);
        v = fma2(q0.y, st1b, v);
        v = fma2(q1.x, dyb[0], v); v = fma2(q1.y, dyb[1], v);
        v = fma2(q2.x, dyb[2], v); v = fma2(q2.y, dyb[3], v);
        v = fma2(q3.x, dyb[4], v); v = fma2(q3.y, dyb[5], v);
        v = fma2(q4.x, dyb[6], v); v = fma2(q4.y, dyb[7], v);
        acc1 = fma2(q5.y, tanh2(v), acc1);
    }
    float a0, a1, b0, b1;
    unpack2(acc0, a0, a1);
    unpack2(acc1, b0, b1);
    *(float2*)(g_scoreP + ((size_t)(hh_*A_*B_ + ab))*S_ + s) = make_float2(a0 + a1, b0 + b1);
}

// =============================================================================
// kfinal: softmax + context + pointer head. grid A*B, block 256 (2 s/thread)
// =============================================================================
__global__ void kfinal(const float* __restrict__ stat,
                       const float* __restrict__ vp,
                       float* __restrict__ out) {
    __shared__ float sC[256*8];
    __shared__ float red[32];
    __shared__ float sP[2];
    int ab = blockIdx.x;
    int a = ab >> 5, b = ab & 31;
    int tid = threadIdx.x, warp = tid >> 5, lane = tid & 31;
    int s = tid*2;

    float2 scA = *(const float2*)(g_scoreP + (size_t)ab*S_ + s);
    float2 scB = *(const float2*)(g_scoreP + ((size_t)(A_*B_ + ab))*S_ + s);
    float2 sc  = make_float2(scA.x + scB.x, scA.y + scB.y);
    float2 st0p = *(const float2*)(stat + ((size_t)b*2+0)*S_ + s);
    float2 st1p = *(const float2*)(stat + ((size_t)b*2+1)*S_ + s);

    float m = fmaxf(sc.x, sc.y);
#pragma unroll
    for (int o = 16; o; o >>= 1) m = fmaxf(m, __shfl_xor_sync(0xffffffffu, m, o));
    if (lane == 0) red[warp] = m;
    __syncthreads();
    float mx = red[0];
#pragma unroll
    for (int w = 1; w < 8; w++) mx = fmaxf(mx, red[w]);
    __syncthreads();

    float e0 = __expf(sc.x - mx), e1 = __expf(sc.y - mx);
    float d  = e0 + e1;
    float n0 = fmaf(e0, st0p.x, e1*st0p.y);
    float n1 = fmaf(e0, st1p.x, e1*st1p.y);
#pragma unroll
    for (int o = 16; o; o >>= 1) {
        d  += __shfl_xor_sync(0xffffffffu, d , o);
        n0 += __shfl_xor_sync(0xffffffffu, n0, o);
        n1 += __shfl_xor_sync(0xffffffffu, n1, o);
    }
    if (lane == 0) { red[warp] = d; red[8+warp] = n0; red[16+warp] = n1; }
    __syncthreads();
    if (tid == 0) {
        float D = 0.f, N0 = 0.f, N1 = 0.f;
#pragma unroll
        for (int w = 0; w < 8; w++) { D += red[w]; N0 += red[8+w]; N1 += red[16+w]; }
        sP[0] = N0 / D; sP[1] = N1 / D;
    }
    __syncthreads();
    float p0 = sP[0], p1 = sP[1];

    {
        int hp = tid, h0 = hp*2;
        int r0 = a*H_ + h0, r1 = r0 + 1;
        float d0 = fmaf(g_N2[r0*2+0], p0, fmaf(g_N2[r0*2+1], p1, g_kk[r0]));
        float d1 = fmaf(g_N2[r1*2+0], p0, fmaf(g_N2[r1*2+1], p1, g_kk[r1]));
        float* p = sC + hp*8;
        p[0] = g_N1[r0*2+0]; p[1] = g_N1[r1*2+0];
        p[2] = g_N1[r0*2+1]; p[3] = g_N1[r1*2+1];
        p[4] = d0; p[5] = d1; p[6] = vp[r0]; p[7] = vp[r1];
    }
    __syncthreads();

    u64 st0a = bcast2(st0p.x), st0b = bcast2(st0p.y);
    u64 st1a = bcast2(st1p.x), st1b = bcast2(st1p.y);

    u64 acc0 = 0ull, acc1 = 0ull;
#pragma unroll 4
    for (int hp = 0; hp < 256; hp++) {
        const U2* cp = (const U2*)(sC + hp*8);
        U2 q0 = cp[0], q1 = cp[1];
        u64 u = fma2(q0.x, st0a, q1.x);
        u = fma2(q0.y, st1a, u);
        acc0 = fma2(q1.y, tanh2(u), acc0);
        u64 v = fma2(q0.x, st0b, q1.x);
        v = fma2(q0.y, st1b, v);
        acc1 = fma2(q1.y, tanh2(v), acc1);
    }
    float a0, a1, b0, b1;
    unpack2(acc0, a0, a1);
    unpack2(acc1, b0, b1);
    *(float2*)(out + (size_t)ab*S_ + s) = make_float2(a0 + a1, b0 + b1);
}

// =============================================================================
extern "C" void kernel_launch(void* const* d_in, const int* in_sizes, int n_in,
                              void* d_out, int out_size) {
    const float* stat  = (const float*)d_in[0];
    const float* dyn   = (const float*)d_in[1];
    const float* dec   = (const float*)d_in[2];
    const float* hh    = (const float*)d_in[3];
    const float* Ws    = (const float*)d_in[4];
    const float* bs    = (const float*)d_in[5];
    const float* Wd    = (const float*)d_in[6];
    const float* bd    = (const float*)d_in[7];
    const float* Wdec  = (const float*)d_in[8];
    const float* bdec  = (const float*)d_in[9];
    const float* Wih   = (const float*)d_in[10];
    const float* Whh   = (const float*)d_in[11];
    const float* bih   = (const float*)d_in[12];
    const float* bhh   = (const float*)d_in[13];
    const float* va    = (const float*)d_in[14];
    const float* Wattn = (const float*)d_in[15];
    const float* vp    = (const float*)d_in[16];
    const float* Wptr  = (const float*)d_in[17];
    float* out = (float*)d_out;

    static cudaStream_t sA = nullptr, sB = nullptr;
    static cudaEvent_t evRoot = nullptr, evIH = nullptr, evAP = nullptr;
    if (sA == nullptr) {
        cudaStreamCreateWithFlags(&sA, cudaStreamNonBlocking);
        cudaStreamCreateWithFlags(&sB, cudaStreamNonBlocking);
        cudaEventCreateWithFlags(&evRoot, cudaEventDisableTiming);
        cudaEventCreateWithFlags(&evIH, cudaEventDisableTiming);
        cudaEventCreateWithFlags(&evAP, cudaEventDisableTiming);
    }

    cudaEventRecord(evRoot, 0);
    cudaStreamWaitEvent(sA, evRoot, 0);
    cudaStreamWaitEvent(sB, evRoot, 0);

    kfoldIH<<<1920, 256, 0, sA>>>(Wih, Wdec, bdec, bih);
    cudaEventRecord(evIH, sA);
    kfoldAP<<<640, 256, 0, sB>>>(Wattn, Wptr, Ws, bs, Wd, bd);
    cudaEventRecord(evAP, sB);

    kgh    <<<960, 128>>>(Whh, hh);
    cudaStreamWaitEvent(0, evIH, 0);   // kgates needs P,q
    kgates <<<640, 256>>>(dec, hh, bhh, out);
    kc     <<<640, 128>>>(Wattn, out);
    cudaStreamWaitEvent(0, evAP, 0);   // kscore needs M1,M2,cc
    kscore <<<640, 256>>>(stat, dyn, va);
    kfinal <<<A_*B_, 256>>>(stat, vp, out);
}

// round 17
// speedup vs baseline: 1.4000x; 1.0385x over previous
#include <cuda_runtime.h>
#include <cstdint>

#define A_  10
#define B_  32
#define H_  512
#define H3_ 1536
#define S_  512
#define KSPL 4
#define CSPL 8
#define OUT_HH_OFF (A_*B_*S_)

typedef unsigned long long u64;
struct __align__(16) U2 { u64 x, y; };

// ---------------- scratch -----------------------------------------------
__device__ float g_M1[A_*H_*2];
__device__ float g_M2[A_*H_*8];
__device__ float g_cc[A_*H_];
__device__ float g_N1[A_*H_*2];
__device__ float g_N2[A_*H_*2];
__device__ float g_kk[A_*H_];
__device__ float g_P [A_*H3_*2];
__device__ float g_q [A_*H3_];
__device__ float g_ghp[KSPL*A_*B_*H3_];
__device__ float g_cp [CSPL*A_*B_*H_];
__device__ float g_scoreP[4*A_*B_*S_];   // [hq][ab][s]

// ---------------- helpers -----------------------------------------------
__device__ __forceinline__ u64 pack2(float lo, float hi) {
    u64 r; asm("mov.b64 %0, {%1,%2};" : "=l"(r) : "f"(lo), "f"(hi)); return r;
}
__device__ __forceinline__ u64 bcast2(float x) { return pack2(x, x); }
__device__ __forceinline__ void unpack2(u64 v, float& lo, float& hi) {
    asm("mov.b64 {%0,%1}, %2;" : "=f"(lo), "=f"(hi) : "l"(v));
}
__device__ __forceinline__ u64 fma2(u64 a, u64 b, u64 c) {
    u64 d; asm("fma.rn.f32x2 %0, %1, %2, %3;" : "=l"(d) : "l"(a), "l"(b), "l"(c));
    return d;
}
__device__ __forceinline__ float tanh_ap(float x) {
    float y; asm("tanh.approx.f32 %0, %1;" : "=f"(y) : "f"(x)); return y;
}
__device__ __forceinline__ u64 tanh2(u64 v) {
    float a, b; unpack2(v, a, b);
    return pack2(tanh_ap(a), tanh_ap(b));
}
__device__ __forceinline__ float ftanh(float x) {
    x = fminf(fmaxf(x, -15.f), 15.f);
    float t = __expf(x + x);
    return fmaf(-2.f, __fdividef(1.f, t + 1.f), 1.f);
}
__device__ __forceinline__ float sigm(float x) {
    return __fdividef(1.f, 1.f + __expf(-x));
}

// =============================================================================
// kfoldIH: fold Wih -> P,q. grid 1920 (a x jt), block 256 (8 warps = 8 rows)
// =============================================================================
__global__ void kfoldIH(const float* __restrict__ Wih,
                        const float* __restrict__ Wdec,
                        const float* __restrict__ bdec,
                        const float* __restrict__ bih) {
    __shared__ __align__(16) float4 sDec[H_];
    int blk = blockIdx.x;
    int warp = threadIdx.x >> 5, lane = threadIdx.x & 31;
    int a = blk / 192, jt = blk % 192;
    for (int k = threadIdx.x; k < H_; k += 256) {
        sDec[k] = make_float4(Wdec[((size_t)a*H_ + k)*2 + 0],
                              Wdec[((size_t)a*H_ + k)*2 + 1],
                              bdec[(size_t)a*H_ + k], 0.f);
    }
    __syncthreads();
    int j = jt * 8 + warp;
    const float* row = Wih + ((size_t)a*H3_ + j)*H_;
    float p0 = 0.f, p1 = 0.f, q = 0.f;
#pragma unroll
    for (int i = 0; i < 4; i++) {
        int k0 = lane*4 + i*128;
        float4 w4 = *(const float4*)(row + k0);
        float4 d0 = sDec[k0+0], d1 = sDec[k0+1], d2 = sDec[k0+2], d3 = sDec[k0+3];
        p0 = fmaf(w4.x,d0.x, fmaf(w4.y,d1.x, fmaf(w4.z,d2.x, fmaf(w4.w,d3.x, p0))));
        p1 = fmaf(w4.x,d0.y, fmaf(w4.y,d1.y, fmaf(w4.z,d2.y, fmaf(w4.w,d3.y, p1))));
        q  = fmaf(w4.x,d0.z, fmaf(w4.y,d1.z, fmaf(w4.z,d2.z, fmaf(w4.w,d3.z, q ))));
    }
#pragma unroll
    for (int o = 16; o; o >>= 1) {
        p0 += __shfl_down_sync(0xffffffffu, p0, o);
        p1 += __shfl_down_sync(0xffffffffu, p1, o);
        q  += __shfl_down_sync(0xffffffffu, q , o);
    }
    if (lane == 0) {
        int r = a*H3_ + j;
        g_P[r*2+0] = p0; g_P[r*2+1] = p1;
        g_q[r] = q + bih[r];
    }
}

// =============================================================================
// kfoldAP: fold Wattn(first 2H)/Wptr -> M1,M2,cc,N1,N2,kk. grid 640, block 256
// =============================================================================
__global__ void kfoldAP(const float* __restrict__ Wattn,
                        const float* __restrict__ Wptr,
                        const float* __restrict__ Ws,
                        const float* __restrict__ bs,
                        const float* __restrict__ Wd,
                        const float* __restrict__ bd) {
    __shared__ __align__(16) float4 sMem[H_*3];
    int blk = blockIdx.x;
    int warp = threadIdx.x >> 5, lane = threadIdx.x & 31;
    int a = blk / 64, ht = blk % 64;
    float4* sFold = sMem;
    float4* sWdA  = sMem + H_;
    float4* sWdB  = sMem + 2*H_;
    for (int k = threadIdx.x; k < H_; k += 256) {
        sFold[k] = make_float4(Ws[k*2+0], Ws[k*2+1], bs[k], bd[(size_t)a*H_ + k]);
        const float* wd = Wd + ((size_t)a*H_ + k)*8;
        sWdA[k] = *(const float4*)(wd);
        sWdB[k] = *(const float4*)(wd + 4);
    }
    __syncthreads();
    int h = ht * 8 + warp;
    const float* ra = Wattn + ((size_t)a*H_ + h)*H3_;
    const float* rp = Wptr  + ((size_t)a*H_ + h)*(2*H_);
    float acc[16];
#pragma unroll
    for (int t = 0; t < 16; t++) acc[t] = 0.f;
#pragma unroll
    for (int i = 0; i < 4; i++) {
        int k0 = lane*4 + i*128;
        float4 a1 = *(const float4*)(ra + k0);
        float4 a2 = *(const float4*)(ra + H_ + k0);
        float4 q1 = *(const float4*)(rp + k0);
        float4 q2 = *(const float4*)(rp + H_ + k0);
        float wa1v[4] = {a1.x, a1.y, a1.z, a1.w};
        float wa2v[4] = {a2.x, a2.y, a2.z, a2.w};
        float wp1v[4] = {q1.x, q1.y, q1.z, q1.w};
        float wp2v[4] = {q2.x, q2.y, q2.z, q2.w};
#pragma unroll
        for (int c = 0; c < 4; c++) {
            int k = k0 + c;
            float wa1 = wa1v[c], wa2 = wa2v[c], wp1 = wp1v[c], wp2 = wp2v[c];
            float4 f  = sFold[k];
            float4 dA = sWdA[k];
            float4 dB = sWdB[k];
            acc[0]  = fmaf(wa1, f.x, acc[0]);
            acc[1]  = fmaf(wa1, f.y, acc[1]);
            acc[2]  = fmaf(wa2, dA.x, acc[2]);
            acc[3]  = fmaf(wa2, dA.y, acc[3]);
            acc[4]  = fmaf(wa2, dA.z, acc[4]);
            acc[5]  = fmaf(wa2, dA.w, acc[5]);
            acc[6]  = fmaf(wa2, dB.x, acc[6]);
            acc[7]  = fmaf(wa2, dB.y, acc[7]);
            acc[8]  = fmaf(wa2, dB.z, acc[8]);
            acc[9]  = fmaf(wa2, dB.w, acc[9]);
            acc[10] = fmaf(wa1, f.z, fmaf(wa2, f.w, acc[10]));
            acc[11] = fmaf(wp1, f.x, acc[11]);
            acc[12] = fmaf(wp1, f.y, acc[12]);
            acc[13] = fmaf(wp2, f.x, acc[13]);
            acc[14] = fmaf(wp2, f.y, acc[14]);
            acc[15] = fmaf(wp1 + wp2, f.z, acc[15]);
        }
    }
#pragma unroll
    for (int t = 0; t < 16; t++)
#pragma unroll
        for (int o = 16; o; o >>= 1)
            acc[t] += __shfl_down_sync(0xffffffffu, acc[t], o);
    if (lane == 0) {
        int r = a*H_ + h;
        g_M1[r*2+0] = acc[0];  g_M1[r*2+1] = acc[1];
#pragma unroll
        for (int f = 0; f < 8; f++) g_M2[r*8+f] = acc[2+f];
        g_cc[r] = acc[10];
        g_N1[r*2+0] = acc[11]; g_N1[r*2+1] = acc[12];
        g_N2[r*2+0] = acc[13]; g_N2[r*2+1] = acc[14];
        g_kk[r] = acc[15];
    }
}

// =============================================================================
// kgh: register-tiled GEMV, 64 j-rows/block, 32-wide slabs.
// grid 960 (a x jt24 x ks4), block 128 = 32 jg x 4 bg; thread = 2j x 4bp
// =============================================================================
__global__ void kgh(const float* __restrict__ Whh,
                    const float* __restrict__ hh) {
    __shared__ __align__(16) u64 sH[128*18];   // [k][bp] 18.4KB
    __shared__ float sW[64*33];                // slab [j][k32] 8.4KB
    int tid = threadIdx.x;
    int blk = blockIdx.x;
    int a = blk / 96, rem = blk % 96, jt = rem >> 2, ks = rem & 3;
    int k0 = ks * 128;
    int jg = tid & 31, bg = tid >> 5;

    for (int idx = tid; idx < 128*16; idx += 128) {
        int k = idx & 127, bp = idx >> 7;
        sH[k*18 + bp] = pack2(hh[(size_t)(2*bp  )*H_ + k0 + k],
                              hh[(size_t)(2*bp+1)*H_ + k0 + k]);
    }

    u64 acc[8];
#pragma unroll
    for (int t = 0; t < 8; t++) acc[t] = 0ull;

    int srow = tid & 63, shalf = tid >> 6;     // 64 rows x 2 k-halves
    const float* wbase = Whh + ((size_t)a*H3_ + jt*64)*H_ + k0;
#pragma unroll 1
    for (int slab = 0; slab < 4; slab++) {
        __syncthreads();
        {   // stage w slab: row srow, 16 k (64B contiguous per thread)
            const float4* src = (const float4*)(wbase + (size_t)srow*H_ + slab*32 + shalf*16);
            float* d = sW + srow*33 + shalf*16;
#pragma unroll
            for (int i = 0; i < 4; i++) {
                float4 v = src[i];
                d[i*4+0]=v.x; d[i*4+1]=v.y; d[i*4+2]=v.z; d[i*4+3]=v.w;
            }
        }
        __syncthreads();
#pragma unroll
        for (int kk = 0; kk < 32; kk++) {
            int k = slab*32 + kk;
            u64 w0 = bcast2(sW[(jg     )*33 + kk]);
            u64 w1 = bcast2(sW[(jg + 32)*33 + kk]);
            const U2* hp = (const U2*)(sH + k*18 + bg*4);
            U2 hA = hp[0], hB = hp[1];
            acc[0] = fma2(w0, hA.x, acc[0]);
            acc[1] = fma2(w0, hA.y, acc[1]);
            acc[2] = fma2(w0, hB.x, acc[2]);
            acc[3] = fma2(w0, hB.y, acc[3]);
            acc[4] = fma2(w1, hA.x, acc[4]);
            acc[5] = fma2(w1, hA.y, acc[5]);
            acc[6] = fma2(w1, hB.x, acc[6]);
            acc[7] = fma2(w1, hB.y, acc[7]);
        }
    }

    float* outp = g_ghp + ((size_t)(ks*A_ + a)*B_)*H3_ + jt*64;
#pragma unroll
    for (int jj = 0; jj < 2; jj++) {
        int j = jg + 32*jj;
#pragma unroll
        for (int i = 0; i < 4; i++) {
            int bp = bg*4 + i;
            float lo, hi; unpack2(acc[jj*4+i], lo, hi);
            outp[(size_t)(2*bp  )*H3_ + j] = lo;
            outp[(size_t)(2*bp+1)*H3_ + j] = hi;
        }
    }
}

// =============================================================================
// kgates: GRU -> h_new (output). grid 640 x 256
// =============================================================================
__global__ void kgates(const float* __restrict__ dec,
                       const float* __restrict__ hh,
                       const float* __restrict__ bhh,
                       float* __restrict__ out) {
    int idx = blockIdx.x * 256 + threadIdx.x;
    int h  = idx & (H_-1);
    int ab = idx >> 9;
    int b  = ab & (B_-1);
    int a  = ab >> 5;
    float d0 = dec[b*2+0], d1 = dec[b*2+1];
    int base = a*H3_;
    float gi[3], gh[3];
#pragma unroll
    for (int g = 0; g < 3; g++) {
        int j = base + g*H_ + h;
        gi[g] = fmaf(g_P[j*2+0], d0, fmaf(g_P[j*2+1], d1, g_q[j]));
        float s = bhh[j];
#pragma unroll
        for (int ks = 0; ks < KSPL; ks++)
            s += g_ghp[((size_t)(ks*A_ + a)*B_ + b)*H3_ + g*H_ + h];
        gh[g] = s;
    }
    float r = sigm(gi[0] + gh[0]);
    float z = sigm(gi[1] + gh[1]);
    float n = ftanh(fmaf(r, gh[2], gi[2]));
    float hprev = hh[(size_t)b*H_ + h];
    out[OUT_HH_OFF + (size_t)ab*H_ + h] = fmaf(z, hprev - n, n);
}

// =============================================================================
// kc: c partials, register-tiled, 64 h-rows/block, 32-wide slabs.
// grid 640 (a x ht8 x cs8), block 128 = 32 jg x 4 bg; thread = 2h x 4bp
// =============================================================================
__global__ void kc(const float* __restrict__ Wattn,
                   const float* __restrict__ out) {
    __shared__ __align__(16) u64 sH[64*18];    // 9.2KB
    __shared__ float sW[64*33];                // 8.4KB
    int tid = threadIdx.x;
    int blk = blockIdx.x;
    int a = blk / 64, rem = blk % 64, ht = rem >> 3, cs = rem & 7;
    int k0 = cs * 64;
    int jg = tid & 31, bg = tid >> 5;
    const float* hn = out + OUT_HH_OFF + (size_t)a*B_*H_;

    for (int idx = tid; idx < 64*16; idx += 128) {
        int k = idx & 63, bp = idx >> 6;
        sH[k*18 + bp] = pack2(hn[(size_t)(2*bp  )*H_ + k0 + k],
                              hn[(size_t)(2*bp+1)*H_ + k0 + k]);
    }

    u64 acc[8];
#pragma unroll
    for (int t = 0; t < 8; t++) acc[t] = 0ull;

    int srow = tid & 63, shalf = tid >> 6;
    const float* wbase = Wattn + ((size_t)(a*H_ + ht*64))*H3_ + 2*H_ + k0;
#pragma unroll 1
    for (int slab = 0; slab < 2; slab++) {
        __syncthreads();
        {
            const float4* src = (const float4*)(wbase + (size_t)srow*H3_ + slab*32 + shalf*16);
            float* d = sW + srow*33 + shalf*16;
#pragma unroll
            for (int i = 0; i < 4; i++) {
                float4 v = src[i];
                d[i*4+0]=v.x; d[i*4+1]=v.y; d[i*4+2]=v.z; d[i*4+3]=v.w;
            }
        }
        __syncthreads();
#pragma unroll
        for (int kk = 0; kk < 32; kk++) {
            int k = slab*32 + kk;
            u64 w0 = bcast2(sW[(jg     )*33 + kk]);
            u64 w1 = bcast2(sW[(jg + 32)*33 + kk]);
            const U2* hp = (const U2*)(sH + k*18 + bg*4);
            U2 hA = hp[0], hB = hp[1];
            acc[0] = fma2(w0, hA.x, acc[0]);
            acc[1] = fma2(w0, hA.y, acc[1]);
            acc[2] = fma2(w0, hB.x, acc[2]);
            acc[3] = fma2(w0, hB.y, acc[3]);
            acc[4] = fma2(w1, hA.x, acc[4]);
            acc[5] = fma2(w1, hA.y, acc[5]);
            acc[6] = fma2(w1, hB.x, acc[6]);
            acc[7] = fma2(w1, hB.y, acc[7]);
        }
    }

    float* outp = g_cp + ((size_t)(cs*A_ + a)*B_)*H_ + ht*64;
#pragma unroll
    for (int jj = 0; jj < 2; jj++) {
        int h = jg + 32*jj;
#pragma unroll
        for (int i = 0; i < 4; i++) {
            int bp = bg*4 + i;
            float lo, hi; unpack2(acc[jj*4+i], lo, hi);
            outp[(size_t)(2*bp  )*H_ + h] = lo;
            outp[(size_t)(2*bp+1)*H_ + h] = hi;
        }
    }
}

// =============================================================================
// kscore: attention scores split over h-quarters.
// grid 1280 (ab x hq4), block 256 (2 s per thread), 6KB smem
// =============================================================================
__global__ void kscore(const float* __restrict__ stat,
                       const float* __restrict__ dyn,
                       const float* __restrict__ va) {
    __shared__ __align__(16) float sC[64*24];
    int blk = blockIdx.x;
    int hq = blk & 3, ab = blk >> 2;
    int a = ab >> 5, b = ab & 31;
    int tid = threadIdx.x;

    if (tid < 64) {
        int hp = tid;
        int h0 = hq*128 + hp*2;
        int r0 = a*H_ + h0, r1 = r0 + 1;
        float c0v = g_cc[r0], c1v = g_cc[r1];
#pragma unroll
        for (int cs = 0; cs < CSPL; cs++) {
            const float* cp = g_cp + ((size_t)(cs*A_ + a)*B_ + b)*H_ + h0;
            c0v += cp[0]; c1v += cp[1];
        }
        float* p = sC + hp*24;
        p[0] = g_M1[r0*2+0]; p[1] = g_M1[r1*2+0];
        p[2] = g_M1[r0*2+1]; p[3] = g_M1[r1*2+1];
#pragma unroll
        for (int f = 0; f < 8; f++) { p[4+2*f] = g_M2[r0*8+f]; p[5+2*f] = g_M2[r1*8+f]; }
        p[20] = c0v; p[21] = c1v; p[22] = va[r0]; p[23] = va[r1];
    }
    __syncthreads();

    int s = tid*2;
    float2 st0p = *(const float2*)(stat + ((size_t)b*2+0)*S_ + s);
    float2 st1p = *(const float2*)(stat + ((size_t)b*2+1)*S_ + s);
    u64 st0a = bcast2(st0p.x), st0b = bcast2(st0p.y);
    u64 st1a = bcast2(st1p.x), st1b = bcast2(st1p.y);
    u64 dya[8], dyb[8];
#pragma unroll
    for (int f = 0; f < 8; f++) {
        float2 d = *(const float2*)(dyn + (((size_t)a*B_ + b)*8 + f)*S_ + s);
        dya[f] = bcast2(d.x); dyb[f] = bcast2(d.y);
    }

    u64 acc0 = 0ull, acc1 = 0ull;
#pragma unroll 2
    for (int hp = 0; hp < 64; hp++) {
        const U2* cp = (const U2*)(sC + hp*24);
        U2 q0 = cp[0], q1 = cp[1], q2 = cp[2], q3 = cp[3], q4 = cp[4], q5 = cp[5];
        u64 u = fma2(q0.x, st0a, q5.x);
        u = fma2(q0.y, st1a, u);
        u = fma2(q1.x, dya[0], u); u = fma2(q1.y, dya[1], u);
        u = fma2(q2.x, dya[2], u); u = fma2(q2.y, dya[3], u);
        u = fma2(q3.x, dya[4], u); u = fma2(q3.y, dya[5], u);
        u = fma2(q4.x, dya[6], u); u = fma2(q4.y, dya[7], u);
        acc0 = fma2(q5.y, tanh2(u), acc0);
        u64 v = fma2(q0.x, st0b, q5.x);
        v = fma2(q0.y, st1b, v);
        v = fma2(q1.x, dyb[0], v); v = fma2(q1.y, dyb[1], v);
        v = fma2(q2.x, dyb[2], v); v = fma2(q2.y, dyb[3], v);
        v = fma2(q3.x, dyb[4], v); v = fma2(q3.y, dyb[5], v);
        v = fma2(q4.x, dyb[6], v); v = fma2(q4.y, dyb[7], v);
        acc1 = fma2(q5.y, tanh2(v), acc1);
    }
    float a0, a1, b0, b1;
    unpack2(acc0, a0, a1);
    unpack2(acc1, b0, b1);
    *(float2*)(g_scoreP + ((size_t)(hq*A_*B_ + ab))*S_ + s) = make_float2(a0 + a1, b0 + b1);
}

// =============================================================================
// kfinal: softmax + context + pointer head. grid A*B, block 256 (2 s/thread)
// =============================================================================
__global__ void kfinal(const float* __restrict__ stat,
                       const float* __restrict__ vp,
                       float* __restrict__ out) {
    __shared__ float sC[256*8];
    __shared__ float red[32];
    __shared__ float sP[2];
    int ab = blockIdx.x;
    int a = ab >> 5, b = ab & 31;
    int tid = threadIdx.x, warp = tid >> 5, lane = tid & 31;
    int s = tid*2;

    float2 sc = make_float2(0.f, 0.f);
#pragma unroll
    for (int hq = 0; hq < 4; hq++) {
        float2 p = *(const float2*)(g_scoreP + ((size_t)(hq*A_*B_ + ab))*S_ + s);
        sc.x += p.x; sc.y += p.y;
    }
    float2 st0p = *(const float2*)(stat + ((size_t)b*2+0)*S_ + s);
    float2 st1p = *(const float2*)(stat + ((size_t)b*2+1)*S_ + s);

    float m = fmaxf(sc.x, sc.y);
#pragma unroll
    for (int o = 16; o; o >>= 1) m = fmaxf(m, __shfl_xor_sync(0xffffffffu, m, o));
    if (lane == 0) red[warp] = m;
    __syncthreads();
    float mx = red[0];
#pragma unroll
    for (int w = 1; w < 8; w++) mx = fmaxf(mx, red[w]);
    __syncthreads();

    float e0 = __expf(sc.x - mx), e1 = __expf(sc.y - mx);
    float d  = e0 + e1;
    float n0 = fmaf(e0, st0p.x, e1*st0p.y);
    float n1 = fmaf(e0, st1p.x, e1*st1p.y);
#pragma unroll
    for (int o = 16; o; o >>= 1) {
        d  += __shfl_xor_sync(0xffffffffu, d , o);
        n0 += __shfl_xor_sync(0xffffffffu, n0, o);
        n1 += __shfl_xor_sync(0xffffffffu, n1, o);
    }
    if (lane == 0) { red[warp] = d; red[8+warp] = n0; red[16+warp] = n1; }
    __syncthreads();
    if (tid == 0) {
        float D = 0.f, N0 = 0.f, N1 = 0.f;
#pragma unroll
        for (int w = 0; w < 8; w++) { D += red[w]; N0 += red[8+w]; N1 += red[16+w]; }
        sP[0] = N0 / D; sP[1] = N1 / D;
    }
    __syncthreads();
    float p0 = sP[0], p1 = sP[1];

    {
        int hp = tid, h0 = hp*2;
        int r0 = a*H_ + h0, r1 = r0 + 1;
        float d0 = fmaf(g_N2[r0*2+0], p0, fmaf(g_N2[r0*2+1], p1, g_kk[r0]));
        float d1 = fmaf(g_N2[r1*2+0], p0, fmaf(g_N2[r1*2+1], p1, g_kk[r1]));
        float* p = sC + hp*8;
        p[0] = g_N1[r0*2+0]; p[1] = g_N1[r1*2+0];
        p[2] = g_N1[r0*2+1]; p[3] = g_N1[r1*2+1];
        p[4] = d0; p[5] = d1; p[6] = vp[r0]; p[7] = vp[r1];
    }
    __syncthreads();

    u64 st0a = bcast2(st0p.x), st0b = bcast2(st0p.y);
    u64 st1a = bcast2(st1p.x), st1b = bcast2(st1p.y);

    u64 acc0 = 0ull, acc1 = 0ull;
#pragma unroll 4
    for (int hp = 0; hp < 256; hp++) {
        const U2* cp = (const U2*)(sC + hp*8);
        U2 q0 = cp[0], q1 = cp[1];
        u64 u = fma2(q0.x, st0a, q1.x);
        u = fma2(q0.y, st1a, u);
        acc0 = fma2(q1.y, tanh2(u), acc0);
        u64 v = fma2(q0.x, st0b, q1.x);
        v = fma2(q0.y, st1b, v);
        acc1 = fma2(q1.y, tanh2(v), acc1);
    }
    float a0, a1, b0, b1;
    unpack2(acc0, a0, a1);
    unpack2(acc1, b0, b1);
    *(float2*)(out + (size_t)ab*S_ + s) = make_float2(a0 + a1, b0 + b1);
}

// =============================================================================
extern "C" void kernel_launch(void* const* d_in, const int* in_sizes, int n_in,
                              void* d_out, int out_size) {
    const float* stat  = (const float*)d_in[0];
    const float* dyn   = (const float*)d_in[1];
    const float* dec   = (const float*)d_in[2];
    const float* hh    = (const float*)d_in[3];
    const float* Ws    = (const float*)d_in[4];
    const float* bs    = (const float*)d_in[5];
    const float* Wd    = (const float*)d_in[6];
    const float* bd    = (const float*)d_in[7];
    const float* Wdec  = (const float*)d_in[8];
    const float* bdec  = (const float*)d_in[9];
    const float* Wih   = (const float*)d_in[10];
    const float* Whh   = (const float*)d_in[11];
    const float* bih   = (const float*)d_in[12];
    const float* bhh   = (const float*)d_in[13];
    const float* va    = (const float*)d_in[14];
    const float* Wattn = (const float*)d_in[15];
    const float* vp    = (const float*)d_in[16];
    const float* Wptr  = (const float*)d_in[17];
    float* out = (float*)d_out;

    static cudaStream_t sA = nullptr, sB = nullptr;
    static cudaEvent_t evRoot = nullptr, evIH = nullptr, evAP = nullptr;
    if (sA == nullptr) {
        cudaStreamCreateWithFlags(&sA, cudaStreamNonBlocking);
        cudaStreamCreateWithFlags(&sB, cudaStreamNonBlocking);
        cudaEventCreateWithFlags(&evRoot, cudaEventDisableTiming);
        cudaEventCreateWithFlags(&evIH, cudaEventDisableTiming);
        cudaEventCreateWithFlags(&evAP, cudaEventDisableTiming);
    }

    cudaEventRecord(evRoot, 0);
    cudaStreamWaitEvent(sA, evRoot, 0);
    cudaStreamWaitEvent(sB, evRoot, 0);

    kfoldIH<<<1920, 256, 0, sA>>>(Wih, Wdec, bdec, bih);
    cudaEventRecord(evIH, sA);
    kfoldAP<<<640, 256, 0, sB>>>(Wattn, Wptr, Ws, bs, Wd, bd);
    cudaEventRecord(evAP, sB);

    kgh    <<<960, 128>>>(Whh, hh);
    cudaStreamWaitEvent(0, evIH, 0);   // kgates needs P,q
    kgates <<<640, 256>>>(dec, hh, bhh, out);
    kc     <<<640, 128>>>(Wattn, out);
    cudaStreamWaitEvent(0, evAP, 0);   // kscore needs M1,M2,cc
    kscore <<<1280, 256>>>(stat, dyn, va);
    kfinal <<<A_*B_, 256>>>(stat, vp, out);
}